// round 9
// baseline (speedup 1.0000x reference)
#include <cuda_runtime.h>
#include <math_constants.h>
#include <cstdint>

#define BB 4
#define SS 2048
#define DD 1024
#define HH 16
#define DKK 64
#define BS_ROWS (BB*SS)   // 8192

// Persistent scratch (allocation-free rule: __device__ globals)
__device__ float g_Q[(size_t)BS_ROWS * DD];
__device__ float g_K[(size_t)BS_ROWS * DD];
__device__ float g_V[(size_t)BS_ROWS * DD];
__device__ float g_A[(size_t)BS_ROWS * DD];

__device__ __forceinline__ uint32_t f2tf32(float x) {
    uint32_t u;
    asm("cvt.rna.tf32.f32 %0, %1;" : "=r"(u) : "f"(x));
    return u;
}

__device__ __forceinline__ float ex2f(float x) {
    float y;
    asm("ex2.approx.f32 %0, %1;" : "=f"(y) : "f"(x));
    return y;
}

__device__ __forceinline__ uint32_t smem_u32(const void* p) {
    uint32_t a;
    asm("{ .reg .u64 t; cvta.to.shared.u64 t, %1; cvt.u32.u64 %0, t; }"
        : "=r"(a) : "l"(p));
    return a;
}

__device__ __forceinline__ void cp_async16(uint32_t saddr, const void* gptr) {
    asm volatile("cp.async.ca.shared.global [%0], [%1], 16;"
                 :: "r"(saddr), "l"(gptr));
}
#define CP_COMMIT() asm volatile("cp.async.commit_group;" ::: "memory")
#define CP_WAIT1()  asm volatile("cp.async.wait_group 1;" ::: "memory")
#define CP_WAIT0()  asm volatile("cp.async.wait_group 0;" ::: "memory")

__device__ __forceinline__ void mma_tf32(float& c0, float& c1, float& c2, float& c3,
                                         uint32_t a0, uint32_t a1, uint32_t a2, uint32_t a3,
                                         uint32_t b0, uint32_t b1) {
    asm volatile(
        "mma.sync.aligned.m16n8k8.row.col.f32.tf32.tf32.f32 "
        "{%0,%1,%2,%3}, {%4,%5,%6,%7}, {%8,%9}, {%0,%1,%2,%3};"
        : "+f"(c0), "+f"(c1), "+f"(c2), "+f"(c3)
        : "r"(a0), "r"(a1), "r"(a2), "r"(a3), "r"(b0), "r"(b1));
}

// ===========================================================================
// Tensor-core GEMM-NT (tf32 mma.sync, cp.async 2-stage pipeline):
// C[M,N] = A[M,K] * Bw[N,K]^T.  BM=BN=128, BK=32, 256 threads.
// Raw fp32 staged in smem; cvt.rna.tf32 in the fragment path.
// ===========================================================================
#define BKG 32
#define GPAD 36
#define G_SMEM (4 * 128 * GPAD * 4)   // 2 stages x (A+B) x 128x36 fp32 = 73728 B

__global__ __launch_bounds__(256, 2)
void gemm_tf32(const float* __restrict__ A, const float* __restrict__ Bw,
               float* __restrict__ C, int M, int N, int K)
{
    extern __shared__ float gsm[];
    float* As = gsm;                   // [2][128][GPAD]
    float* Bs = gsm + 2 * 128 * GPAD;  // [2][128][GPAD]

    const int t    = threadIdx.x;
    const int wid  = t >> 5;
    const int lane = t & 31;
    const int g    = lane >> 2;
    const int tg   = lane & 3;
    const int warp_m = wid & 3;
    const int warp_n = wid >> 2;

    const int rowBase = blockIdx.y * 128;
    const int colBase = blockIdx.x * 128;

    const float* Ag = A  + (size_t)rowBase * K;
    const float* Bg = Bw + (size_t)colBase * K;

    const int lr0 = t >> 3;          // 0..31
    const int lc4 = (t & 7) << 2;    // 0,4,..,28

    float acc[2][8][4];
#pragma unroll
    for (int mt = 0; mt < 2; ++mt)
#pragma unroll
        for (int nt = 0; nt < 8; ++nt)
#pragma unroll
            for (int i = 0; i < 4; ++i) acc[mt][nt][i] = 0.f;

    const int NIT = K / BKG;   // 32

    // Prologue: stage 0
#pragma unroll
    for (int p = 0; p < 4; ++p) {
        int r = p * 32 + lr0;
        cp_async16(smem_u32(&As[(size_t)r * GPAD + lc4]),
                   Ag + (size_t)r * K + lc4);
        cp_async16(smem_u32(&Bs[(size_t)r * GPAD + lc4]),
                   Bg + (size_t)r * K + lc4);
    }
    CP_COMMIT();

    for (int kt = 0; kt < NIT; ++kt) {
        if (kt + 1 < NIT) {
            const int s1 = (kt + 1) & 1;
            const int k1 = (kt + 1) * BKG;
#pragma unroll
            for (int p = 0; p < 4; ++p) {
                int r = p * 32 + lr0;
                cp_async16(smem_u32(&As[(size_t)(s1 * 128 + r) * GPAD + lc4]),
                           Ag + (size_t)r * K + k1 + lc4);
                cp_async16(smem_u32(&Bs[(size_t)(s1 * 128 + r) * GPAD + lc4]),
                           Bg + (size_t)r * K + k1 + lc4);
            }
            CP_COMMIT();
            CP_WAIT1();
        } else {
            CP_WAIT0();
        }
        __syncthreads();

        const int sb = (kt & 1) * 128;
#pragma unroll
        for (int kk = 0; kk < 4; ++kk) {
            const int ks = kk << 3;
            uint32_t afr[2][4];
#pragma unroll
            for (int mt = 0; mt < 2; ++mt) {
                const float* ar = &As[(size_t)(sb + warp_m * 32 + mt * 16 + g) * GPAD + ks + tg];
                afr[mt][0] = f2tf32(ar[0]);
                afr[mt][1] = f2tf32(ar[8 * GPAD]);
                afr[mt][2] = f2tf32(ar[4]);
                afr[mt][3] = f2tf32(ar[8 * GPAD + 4]);
            }
#pragma unroll
            for (int nt = 0; nt < 8; ++nt) {
                const float* br = &Bs[(size_t)(sb + warp_n * 64 + nt * 8 + g) * GPAD + ks + tg];
                uint32_t b0 = f2tf32(br[0]);
                uint32_t b1 = f2tf32(br[4]);
#pragma unroll
                for (int mt = 0; mt < 2; ++mt)
                    mma_tf32(acc[mt][nt][0], acc[mt][nt][1],
                             acc[mt][nt][2], acc[mt][nt][3],
                             afr[mt][0], afr[mt][1], afr[mt][2], afr[mt][3],
                             b0, b1);
            }
        }
        __syncthreads();
    }

#pragma unroll
    for (int mt = 0; mt < 2; ++mt) {
        const int r0 = rowBase + warp_m * 32 + mt * 16 + g;
#pragma unroll
        for (int nt = 0; nt < 8; ++nt) {
            const int c = colBase + warp_n * 64 + nt * 8 + tg * 2;
            *(float2*)(C + (size_t)r0 * N + c) =
                make_float2(acc[mt][nt][0], acc[mt][nt][1]);
            *(float2*)(C + (size_t)(r0 + 8) * N + c) =
                make_float2(acc[mt][nt][2], acc[mt][nt][3]);
        }
    }
}

// ---------------------------------------------------------------------------
// RoPE (in place).
// ---------------------------------------------------------------------------
__global__ void rope_kernel(float* __restrict__ q, const int* __restrict__ pos)
{
    int i = blockIdx.x * blockDim.x + threadIdx.x;
    if (i >= BS_ROWS * 512) return;
    int row = i >> 9;
    int p   = i & 511;
    int j   = p & 31;
    int s   = row & (SS - 1);
    float posv = (float)pos[s];
    float inv = expf(-(float)j * 0.28782313662425572f);
    float ang = posv * inv;
    float sn, cs;
    sincosf(ang, &sn, &cs);
    size_t base = (size_t)row * DD + (size_t)(p << 1);
    float x1 = q[base + 0];
    float x2 = q[base + 1];
    q[base + 0] = x1 * cs - x2 * sn;
    q[base + 1] = x1 * sn + x2 * cs;
}

// ===========================================================================
// Tensor-core flash attention (causal), 3x-tf32 error-compensated.
// Br=128, Bc=64, 256 threads (8 warps), warp owns 16 query rows.
// smem: KsH/KsL/VsH/VsL 64x68, PsH/PsL 128x68 (u32, padded). 139264 B.
// ===========================================================================
#define FP 68
#define F_SMEM ((4 * 64 + 2 * 128) * FP * 4)   // 139264 B

__global__ __launch_bounds__(256, 1)
void flash_mma(const float* __restrict__ Q, const float* __restrict__ K,
               const float* __restrict__ V, float* __restrict__ O)
{
    extern __shared__ uint32_t fsm[];
    uint32_t* KsH = fsm;
    uint32_t* KsL = KsH + 64 * FP;
    uint32_t* VsH = KsL + 64 * FP;
    uint32_t* VsL = VsH + 64 * FP;
    uint32_t* PsH = VsL + 64 * FP;    // 128 rows
    uint32_t* PsL = PsH + 128 * FP;   // 128 rows

    const int t    = threadIdx.x;
    const int wid  = t >> 5;
    const int lane = t & 31;
    const int g    = lane >> 2;
    const int tg   = lane & 3;
    const int qbase = blockIdx.x * 128;

    const size_t hb = (size_t)blockIdx.z * SS * DD + (size_t)blockIdx.y * DKK;
    const float* Qg = Q + hb;
    const float* Kg = K + hb;
    const float* Vg = V + hb;
    float*       Og = O + hb;

    const float QS = 0.125f * 1.4426950408889634f;   // 1/sqrt(64) * log2(e)

    // Stage Q (scaled) hi/lo into PsH/PsL, then pull fragments to registers
#pragma unroll
    for (int p = 0; p < 8; ++p) {
        int idx = p * 256 + t;               // 0..2047
        int r = idx >> 4, c = (idx & 15) << 2;
        float4 v = *(const float4*)(Qg + (size_t)(qbase + r) * DD + c);
        float f0 = v.x * QS, f1 = v.y * QS, f2 = v.z * QS, f3 = v.w * QS;
        uint4 h, l;
        h.x = f2tf32(f0); l.x = f2tf32(f0 - __uint_as_float(h.x));
        h.y = f2tf32(f1); l.y = f2tf32(f1 - __uint_as_float(h.y));
        h.z = f2tf32(f2); l.z = f2tf32(f2 - __uint_as_float(h.z));
        h.w = f2tf32(f3); l.w = f2tf32(f3 - __uint_as_float(h.w));
        *(uint4*)&PsH[r * FP + c] = h;
        *(uint4*)&PsL[r * FP + c] = l;
    }
    __syncthreads();

    uint32_t qh[8][4], ql[8][4];
    const int arow = wid * 16 + g;
#pragma unroll
    for (int ks = 0; ks < 8; ++ks) {
        int kc = ks * 8 + tg;
        qh[ks][0] = PsH[arow * FP + kc];
        qh[ks][1] = PsH[(arow + 8) * FP + kc];
        qh[ks][2] = PsH[arow * FP + kc + 4];
        qh[ks][3] = PsH[(arow + 8) * FP + kc + 4];
        ql[ks][0] = PsL[arow * FP + kc];
        ql[ks][1] = PsL[(arow + 8) * FP + kc];
        ql[ks][2] = PsL[arow * FP + kc + 4];
        ql[ks][3] = PsL[(arow + 8) * FP + kc + 4];
    }
    __syncthreads();

    float m0 = -CUDART_INF_F, m1 = -CUDART_INF_F, l0 = 0.f, l1 = 0.f;
    float o[8][4];
#pragma unroll
    for (int nt = 0; nt < 8; ++nt)
#pragma unroll
        for (int i = 0; i < 4; ++i) o[nt][i] = 0.f;

    const int nkt = 2 * blockIdx.x + 2;
    for (int kt = 0; kt < nkt; ++kt) {
        const int kb = kt * 64;

        // Load K, V tiles (64 x 64), hi/lo split
#pragma unroll
        for (int p = 0; p < 4; ++p) {
            int idx = p * 256 + t;               // 0..1023
            int r = idx >> 4, c = (idx & 15) << 2;
            float4 kv = *(const float4*)(Kg + (size_t)(kb + r) * DD + c);
            float4 vv = *(const float4*)(Vg + (size_t)(kb + r) * DD + c);
            uint4 kh, kl, vh, vl;
            kh.x = f2tf32(kv.x); kl.x = f2tf32(kv.x - __uint_as_float(kh.x));
            kh.y = f2tf32(kv.y); kl.y = f2tf32(kv.y - __uint_as_float(kh.y));
            kh.z = f2tf32(kv.z); kl.z = f2tf32(kv.z - __uint_as_float(kh.z));
            kh.w = f2tf32(kv.w); kl.w = f2tf32(kv.w - __uint_as_float(kh.w));
            vh.x = f2tf32(vv.x); vl.x = f2tf32(vv.x - __uint_as_float(vh.x));
            vh.y = f2tf32(vv.y); vl.y = f2tf32(vv.y - __uint_as_float(vh.y));
            vh.z = f2tf32(vv.z); vl.z = f2tf32(vv.z - __uint_as_float(vh.z));
            vh.w = f2tf32(vv.w); vl.w = f2tf32(vv.w - __uint_as_float(vh.w));
            *(uint4*)&KsH[r * FP + c] = kh;
            *(uint4*)&KsL[r * FP + c] = kl;
            *(uint4*)&VsH[r * FP + c] = vh;
            *(uint4*)&VsL[r * FP + c] = vl;
        }
        __syncthreads();

        // S = (Q * scale) K^T  -- 3x tf32
        float s[8][4];
#pragma unroll
        for (int nt = 0; nt < 8; ++nt)
#pragma unroll
            for (int i = 0; i < 4; ++i) s[nt][i] = 0.f;

#pragma unroll
        for (int ks = 0; ks < 8; ++ks) {
            const int kc = ks * 8;
#pragma unroll
            for (int nt = 0; nt < 8; ++nt) {
                const int br = (nt * 8 + g) * FP + kc;
                uint32_t bh0 = KsH[br + tg], bh1 = KsH[br + tg + 4];
                uint32_t bl0 = KsL[br + tg], bl1 = KsL[br + tg + 4];
                mma_tf32(s[nt][0], s[nt][1], s[nt][2], s[nt][3],
                         qh[ks][0], qh[ks][1], qh[ks][2], qh[ks][3], bh0, bh1);
                mma_tf32(s[nt][0], s[nt][1], s[nt][2], s[nt][3],
                         ql[ks][0], ql[ks][1], ql[ks][2], ql[ks][3], bh0, bh1);
                mma_tf32(s[nt][0], s[nt][1], s[nt][2], s[nt][3],
                         qh[ks][0], qh[ks][1], qh[ks][2], qh[ks][3], bl0, bl1);
            }
        }

        // Causal mask (only tiles straddling the diagonal for this warp)
        const int row0 = qbase + wid * 16 + g;
        if (kb + 63 > row0) {
#pragma unroll
            for (int nt = 0; nt < 8; ++nt) {
                const int c0 = kb + nt * 8 + 2 * tg;
                if (c0     > row0)     s[nt][0] = -CUDART_INF_F;
                if (c0 + 1 > row0)     s[nt][1] = -CUDART_INF_F;
                if (c0     > row0 + 8) s[nt][2] = -CUDART_INF_F;
                if (c0 + 1 > row0 + 8) s[nt][3] = -CUDART_INF_F;
            }
        }

        // Online softmax (exp2 domain)
        float mx0 = -CUDART_INF_F, mx1 = -CUDART_INF_F;
#pragma unroll
        for (int nt = 0; nt < 8; ++nt) {
            mx0 = fmaxf(mx0, fmaxf(s[nt][0], s[nt][1]));
            mx1 = fmaxf(mx1, fmaxf(s[nt][2], s[nt][3]));
        }
        mx0 = fmaxf(mx0, __shfl_xor_sync(0xffffffffu, mx0, 1));
        mx0 = fmaxf(mx0, __shfl_xor_sync(0xffffffffu, mx0, 2));
        mx1 = fmaxf(mx1, __shfl_xor_sync(0xffffffffu, mx1, 1));
        mx1 = fmaxf(mx1, __shfl_xor_sync(0xffffffffu, mx1, 2));

        float mn0 = fmaxf(m0, mx0), mn1 = fmaxf(m1, mx1);
        float cr0 = ex2f(m0 - mn0), cr1 = ex2f(m1 - mn1);
        float sum0 = 0.f, sum1 = 0.f;
        const int prow = (wid * 16 + g) * FP;
#pragma unroll
        for (int nt = 0; nt < 8; ++nt) {
            float p0 = ex2f(s[nt][0] - mn0), p1 = ex2f(s[nt][1] - mn0);
            float p2 = ex2f(s[nt][2] - mn1), p3 = ex2f(s[nt][3] - mn1);
            sum0 += p0 + p1;
            sum1 += p2 + p3;
            uint32_t h0 = f2tf32(p0), h1 = f2tf32(p1);
            uint32_t h2 = f2tf32(p2), h3 = f2tf32(p3);
            const int pc = nt * 8 + 2 * tg;
            *(uint2*)&PsH[prow + pc]          = make_uint2(h0, h1);
            *(uint2*)&PsH[prow + 8 * FP + pc] = make_uint2(h2, h3);
            *(uint2*)&PsL[prow + pc]          = make_uint2(
                f2tf32(p0 - __uint_as_float(h0)), f2tf32(p1 - __uint_as_float(h1)));
            *(uint2*)&PsL[prow + 8 * FP + pc] = make_uint2(
                f2tf32(p2 - __uint_as_float(h2)), f2tf32(p3 - __uint_as_float(h3)));
        }
        sum0 += __shfl_xor_sync(0xffffffffu, sum0, 1);
        sum0 += __shfl_xor_sync(0xffffffffu, sum0, 2);
        sum1 += __shfl_xor_sync(0xffffffffu, sum1, 1);
        sum1 += __shfl_xor_sync(0xffffffffu, sum1, 2);
        l0 = l0 * cr0 + sum0;
        l1 = l1 * cr1 + sum1;
        m0 = mn0; m1 = mn1;
#pragma unroll
        for (int nt = 0; nt < 8; ++nt) {
            o[nt][0] *= cr0; o[nt][1] *= cr0;
            o[nt][2] *= cr1; o[nt][3] *= cr1;
        }
        __syncwarp();

        // O += P V  -- 3x tf32
#pragma unroll
        for (int ks = 0; ks < 8; ++ks) {
            const int kc = ks * 8;
            uint32_t ah0 = PsH[prow + kc + tg];
            uint32_t ah1 = PsH[prow + 8 * FP + kc + tg];
            uint32_t ah2 = PsH[prow + kc + tg + 4];
            uint32_t ah3 = PsH[prow + 8 * FP + kc + tg + 4];
            uint32_t al0 = PsL[prow + kc + tg];
            uint32_t al1 = PsL[prow + 8 * FP + kc + tg];
            uint32_t al2 = PsL[prow + kc + tg + 4];
            uint32_t al3 = PsL[prow + 8 * FP + kc + tg + 4];
#pragma unroll
            for (int nt = 0; nt < 8; ++nt) {
                const int vb = (kc + tg) * FP + nt * 8 + g;
                uint32_t bh0 = VsH[vb], bh1 = VsH[vb + 4 * FP];
                uint32_t bl0 = VsL[vb], bl1 = VsL[vb + 4 * FP];
                mma_tf32(o[nt][0], o[nt][1], o[nt][2], o[nt][3],
                         ah0, ah1, ah2, ah3, bh0, bh1);
                mma_tf32(o[nt][0], o[nt][1], o[nt][2], o[nt][3],
                         al0, al1, al2, al3, bh0, bh1);
                mma_tf32(o[nt][0], o[nt][1], o[nt][2], o[nt][3],
                         ah0, ah1, ah2, ah3, bl0, bl1);
            }
        }
        __syncthreads();
    }

    // Epilogue
    const float i0 = 1.0f / l0, i1 = 1.0f / l1;
    const int row0 = qbase + wid * 16 + g;
#pragma unroll
    for (int nt = 0; nt < 8; ++nt) {
        const int c = nt * 8 + 2 * tg;
        *(float2*)(Og + (size_t)row0 * DD + c) =
            make_float2(o[nt][0] * i0, o[nt][1] * i0);
        *(float2*)(Og + (size_t)(row0 + 8) * DD + c) =
            make_float2(o[nt][2] * i1, o[nt][3] * i1);
    }
}

// ---------------------------------------------------------------------------
extern "C" void kernel_launch(void* const* d_in, const int* in_sizes, int n_in,
                              void* d_out, int out_size)
{
    const float* x   = (const float*)d_in[0];
    const int*   pos = (const int*)  d_in[1];
    const float* Wq  = (const float*)d_in[2];
    const float* Wk  = (const float*)d_in[3];
    const float* Wv  = (const float*)d_in[4];
    const float* Wo  = (const float*)d_in[5];
    float* out = (float*)d_out;

    float *Q, *K, *V, *Aw;
    cudaGetSymbolAddress((void**)&Q,  g_Q);
    cudaGetSymbolAddress((void**)&K,  g_K);
    cudaGetSymbolAddress((void**)&V,  g_V);
    cudaGetSymbolAddress((void**)&Aw, g_A);

    cudaFuncSetAttribute(gemm_tf32, cudaFuncAttributeMaxDynamicSharedMemorySize,
                         G_SMEM);
    cudaFuncSetAttribute(flash_mma, cudaFuncAttributeMaxDynamicSharedMemorySize,
                         F_SMEM);

    dim3 gg(DD / 128, BS_ROWS / 128);   // (8, 64)

    gemm_tf32<<<gg, 256, G_SMEM>>>(x, Wq, Q, BS_ROWS, DD, DD);
    gemm_tf32<<<gg, 256, G_SMEM>>>(x, Wk, K, BS_ROWS, DD, DD);
    gemm_tf32<<<gg, 256, G_SMEM>>>(x, Wv, V, BS_ROWS, DD, DD);

    const int rope_elems = BS_ROWS * 512;
    rope_kernel<<<rope_elems / 256, 256>>>(Q, pos);
    rope_kernel<<<rope_elems / 256, 256>>>(K, pos);

    flash_mma<<<dim3(SS / 128, HH, BB), 256, F_SMEM>>>(Q, K, V, Aw);

    gemm_tf32<<<gg, 256, G_SMEM>>>(Aw, Wo, out, BS_ROWS, DD, DD);
}

// round 10
// speedup vs baseline: 1.0391x; 1.0391x over previous
#include <cuda_runtime.h>
#include <math_constants.h>
#include <cstdint>

#define BB 4
#define SS 2048
#define DD 1024
#define HH 16
#define DKK 64
#define BS_ROWS (BB*SS)   // 8192

// Persistent scratch (allocation-free rule: __device__ globals)
__device__ float g_Q[(size_t)BS_ROWS * DD];
__device__ float g_K[(size_t)BS_ROWS * DD];
__device__ float g_V[(size_t)BS_ROWS * DD];
__device__ float g_A[(size_t)BS_ROWS * DD];

__device__ __forceinline__ uint32_t f2tf32(float x) {
    uint32_t u;
    asm("cvt.rna.tf32.f32 %0, %1;" : "=r"(u) : "f"(x));
    return u;
}

__device__ __forceinline__ float ex2f(float x) {
    float y;
    asm("ex2.approx.f32 %0, %1;" : "=f"(y) : "f"(x));
    return y;
}

__device__ __forceinline__ uint32_t smem_u32(const void* p) {
    uint32_t a;
    asm("{ .reg .u64 t; cvta.to.shared.u64 t, %1; cvt.u32.u64 %0, t; }"
        : "=r"(a) : "l"(p));
    return a;
}

__device__ __forceinline__ void ldsm_x4(uint32_t& r0, uint32_t& r1,
                                        uint32_t& r2, uint32_t& r3,
                                        uint32_t addr) {
    asm volatile("ldmatrix.sync.aligned.m8n8.x4.shared.b16 {%0,%1,%2,%3}, [%4];"
                 : "=r"(r0), "=r"(r1), "=r"(r2), "=r"(r3) : "r"(addr));
}

__device__ __forceinline__ void mma_tf32(float& c0, float& c1, float& c2, float& c3,
                                         uint32_t a0, uint32_t a1, uint32_t a2, uint32_t a3,
                                         uint32_t b0, uint32_t b1) {
    asm volatile(
        "mma.sync.aligned.m16n8k8.row.col.f32.tf32.tf32.f32 "
        "{%0,%1,%2,%3}, {%4,%5,%6,%7}, {%8,%9}, {%0,%1,%2,%3};"
        : "+f"(c0), "+f"(c1), "+f"(c2), "+f"(c3)
        : "r"(a0), "r"(a1), "r"(a2), "r"(a3), "r"(b0), "r"(b1));
}

// ===========================================================================
// Tensor-core GEMM-NT (tf32 mma.sync): C[M,N] = A[M,K] * Bw[N,K]^T
// BM=BN=128, BK=32, 256 threads (4m x 2n warps, warp tile 32x64).
// tf32 staged in smem (cvt at load); ldmatrix.x4 fragment loads;
// register double-buffering of the next K-tile's global loads.
// ===========================================================================
#define BKG 32
#define GPAD 36
#define G_SMEM (2 * 128 * GPAD * 4)   // A+B, tf32, single stage = 36864 B

__global__ __launch_bounds__(256, 2)
void gemm_tf32(const float* __restrict__ A, const float* __restrict__ Bw,
               float* __restrict__ C, int M, int N, int K)
{
    extern __shared__ uint32_t gsm[];
    uint32_t* As = gsm;                // [128][GPAD]
    uint32_t* Bs = gsm + 128 * GPAD;   // [128][GPAD]

    const int t    = threadIdx.x;
    const int wid  = t >> 5;
    const int lane = t & 31;
    const int g    = lane >> 2;
    const int tg   = lane & 3;
    const int warp_m = wid & 3;
    const int warp_n = wid >> 2;

    const int rowBase = blockIdx.y * 128;
    const int colBase = blockIdx.x * 128;

    const float* Ag = A  + (size_t)rowBase * K;
    const float* Bg = Bw + (size_t)colBase * K;

    const int lr0 = t >> 3;          // 0..31
    const int lc4 = (t & 7) << 2;    // 0,4,..,28

    // ldmatrix per-lane row addresses
    const int arow = lane & 15;                       // rows R..R+15
    const int acol = (lane < 16) ? 0 : 4;             // k-words 0 / 4
    const uint32_t aBase0 =
        smem_u32(&As[(size_t)(warp_m * 32 + arow) * GPAD + acol]);
    const uint32_t aBase1 = aBase0 + 16 * GPAD * 4;

    const int brow = ((lane >> 4) << 3) + (lane & 7); // 2 n-tiles per x4
    const int bcol = (lane & 8) ? 4 : 0;
    uint32_t bBase[4];
#pragma unroll
    for (int p = 0; p < 4; ++p)
        bBase[p] = smem_u32(&Bs[(size_t)(warp_n * 64 + p * 16 + brow) * GPAD + bcol]);

    float acc[2][8][4];
#pragma unroll
    for (int mt = 0; mt < 2; ++mt)
#pragma unroll
        for (int nt = 0; nt < 8; ++nt)
#pragma unroll
            for (int i = 0; i < 4; ++i) acc[mt][nt][i] = 0.f;

    const int NIT = K / BKG;   // 32

    // Prologue: load + convert + store tile 0
    float4 stA[4], stB[4];
#pragma unroll
    for (int p = 0; p < 4; ++p) {
        int r = p * 32 + lr0;
        stA[p] = *(const float4*)(Ag + (size_t)r * K + lc4);
        stB[p] = *(const float4*)(Bg + (size_t)r * K + lc4);
    }
#pragma unroll
    for (int p = 0; p < 4; ++p) {
        int r = p * 32 + lr0;
        uint32_t* ad = &As[(size_t)r * GPAD + lc4];
        uint32_t* bd = &Bs[(size_t)r * GPAD + lc4];
        ad[0] = f2tf32(stA[p].x); ad[1] = f2tf32(stA[p].y);
        ad[2] = f2tf32(stA[p].z); ad[3] = f2tf32(stA[p].w);
        bd[0] = f2tf32(stB[p].x); bd[1] = f2tf32(stB[p].y);
        bd[2] = f2tf32(stB[p].z); bd[3] = f2tf32(stB[p].w);
    }
    __syncthreads();

    for (int kt = 0; kt < NIT; ++kt) {
        // Issue next tile's global loads (consumed after compute)
        if (kt + 1 < NIT) {
            const int k1 = (kt + 1) * BKG;
#pragma unroll
            for (int p = 0; p < 4; ++p) {
                int r = p * 32 + lr0;
                stA[p] = *(const float4*)(Ag + (size_t)r * K + k1 + lc4);
                stB[p] = *(const float4*)(Bg + (size_t)r * K + k1 + lc4);
            }
        }

        // Compute current tile from smem via ldmatrix
#pragma unroll
        for (int kk = 0; kk < 4; ++kk) {
            const uint32_t ko = kk * 32;   // bytes: 8 words per kk
            uint32_t af0[4], af1[4];
            ldsm_x4(af0[0], af0[1], af0[2], af0[3], aBase0 + ko);
            ldsm_x4(af1[0], af1[1], af1[2], af1[3], aBase1 + ko);
#pragma unroll
            for (int p = 0; p < 4; ++p) {
                uint32_t b00, b01, b10, b11;
                ldsm_x4(b00, b01, b10, b11, bBase[p] + ko);
                mma_tf32(acc[0][2*p][0], acc[0][2*p][1], acc[0][2*p][2], acc[0][2*p][3],
                         af0[0], af0[1], af0[2], af0[3], b00, b01);
                mma_tf32(acc[1][2*p][0], acc[1][2*p][1], acc[1][2*p][2], acc[1][2*p][3],
                         af1[0], af1[1], af1[2], af1[3], b00, b01);
                mma_tf32(acc[0][2*p+1][0], acc[0][2*p+1][1], acc[0][2*p+1][2], acc[0][2*p+1][3],
                         af0[0], af0[1], af0[2], af0[3], b10, b11);
                mma_tf32(acc[1][2*p+1][0], acc[1][2*p+1][1], acc[1][2*p+1][2], acc[1][2*p+1][3],
                         af1[0], af1[1], af1[2], af1[3], b10, b11);
            }
        }
        __syncthreads();

        // Convert + store next tile
        if (kt + 1 < NIT) {
#pragma unroll
            for (int p = 0; p < 4; ++p) {
                int r = p * 32 + lr0;
                uint32_t* ad = &As[(size_t)r * GPAD + lc4];
                uint32_t* bd = &Bs[(size_t)r * GPAD + lc4];
                ad[0] = f2tf32(stA[p].x); ad[1] = f2tf32(stA[p].y);
                ad[2] = f2tf32(stA[p].z); ad[3] = f2tf32(stA[p].w);
                bd[0] = f2tf32(stB[p].x); bd[1] = f2tf32(stB[p].y);
                bd[2] = f2tf32(stB[p].z); bd[3] = f2tf32(stB[p].w);
            }
            __syncthreads();
        }
    }

#pragma unroll
    for (int mt = 0; mt < 2; ++mt) {
        const int r0 = rowBase + warp_m * 32 + mt * 16 + g;
#pragma unroll
        for (int nt = 0; nt < 8; ++nt) {
            const int c = colBase + warp_n * 64 + nt * 8 + tg * 2;
            *(float2*)(C + (size_t)r0 * N + c) =
                make_float2(acc[mt][nt][0], acc[mt][nt][1]);
            *(float2*)(C + (size_t)(r0 + 8) * N + c) =
                make_float2(acc[mt][nt][2], acc[mt][nt][3]);
        }
    }
}

// ---------------------------------------------------------------------------
// RoPE (in place).
// ---------------------------------------------------------------------------
__global__ void rope_kernel(float* __restrict__ q, const int* __restrict__ pos)
{
    int i = blockIdx.x * blockDim.x + threadIdx.x;
    if (i >= BS_ROWS * 512) return;
    int row = i >> 9;
    int p   = i & 511;
    int j   = p & 31;
    int s   = row & (SS - 1);
    float posv = (float)pos[s];
    float inv = expf(-(float)j * 0.28782313662425572f);
    float ang = posv * inv;
    float sn, cs;
    sincosf(ang, &sn, &cs);
    size_t base = (size_t)row * DD + (size_t)(p << 1);
    float x1 = q[base + 0];
    float x2 = q[base + 1];
    q[base + 0] = x1 * cs - x2 * sn;
    q[base + 1] = x1 * sn + x2 * cs;
}

// ===========================================================================
// Tensor-core flash attention (causal), 3x-tf32 error-compensated.
// Br=Bc=64, 128 threads (4 warps), warp owns 16 query rows.  (R6 version)
// ===========================================================================
#define FP 68
#define F_SMEM (6 * 64 * FP * 4)   // 104448 B

__global__ __launch_bounds__(128, 2)
void flash_mma(const float* __restrict__ Q, const float* __restrict__ K,
               const float* __restrict__ V, float* __restrict__ O)
{
    extern __shared__ uint32_t fsm[];
    uint32_t* KsH = fsm;
    uint32_t* KsL = KsH + 64 * FP;
    uint32_t* VsH = KsL + 64 * FP;
    uint32_t* VsL = VsH + 64 * FP;
    uint32_t* PsH = VsL + 64 * FP;
    uint32_t* PsL = PsH + 64 * FP;

    const int t    = threadIdx.x;
    const int wid  = t >> 5;
    const int lane = t & 31;
    const int g    = lane >> 2;
    const int tg   = lane & 3;
    const int qbase = blockIdx.x * 64;

    const size_t hb = (size_t)blockIdx.z * SS * DD + (size_t)blockIdx.y * DKK;
    const float* Qg = Q + hb;
    const float* Kg = K + hb;
    const float* Vg = V + hb;
    float*       Og = O + hb;

    const float QS = 0.125f * 1.4426950408889634f;   // 1/sqrt(64) * log2(e)

    // Stage Q (scaled) hi/lo into KsH/KsL, then pull fragments to registers
#pragma unroll
    for (int p = 0; p < 8; ++p) {
        int idx = p * 128 + t;
        int r = idx >> 4, c = (idx & 15) << 2;
        float4 v = *(const float4*)(Qg + (size_t)(qbase + r) * DD + c);
        float f0 = v.x * QS, f1 = v.y * QS, f2 = v.z * QS, f3 = v.w * QS;
        uint4 h, l;
        h.x = f2tf32(f0); l.x = f2tf32(f0 - __uint_as_float(h.x));
        h.y = f2tf32(f1); l.y = f2tf32(f1 - __uint_as_float(h.y));
        h.z = f2tf32(f2); l.z = f2tf32(f2 - __uint_as_float(h.z));
        h.w = f2tf32(f3); l.w = f2tf32(f3 - __uint_as_float(h.w));
        *(uint4*)&KsH[r * FP + c] = h;
        *(uint4*)&KsL[r * FP + c] = l;
    }
    __syncthreads();

    uint32_t qh[8][4], ql[8][4];
    const int arow = wid * 16 + g;
#pragma unroll
    for (int ks = 0; ks < 8; ++ks) {
        int kc = ks * 8 + tg;
        qh[ks][0] = KsH[arow * FP + kc];
        qh[ks][1] = KsH[(arow + 8) * FP + kc];
        qh[ks][2] = KsH[arow * FP + kc + 4];
        qh[ks][3] = KsH[(arow + 8) * FP + kc + 4];
        ql[ks][0] = KsL[arow * FP + kc];
        ql[ks][1] = KsL[(arow + 8) * FP + kc];
        ql[ks][2] = KsL[arow * FP + kc + 4];
        ql[ks][3] = KsL[(arow + 8) * FP + kc + 4];
    }
    __syncthreads();

    float m0 = -CUDART_INF_F, m1 = -CUDART_INF_F, l0 = 0.f, l1 = 0.f;
    float o[8][4];
#pragma unroll
    for (int nt = 0; nt < 8; ++nt)
#pragma unroll
        for (int i = 0; i < 4; ++i) o[nt][i] = 0.f;

    for (int kt = 0; kt <= (int)blockIdx.x; ++kt) {
        const int kb = kt * 64;

        // Load K, V tiles, hi/lo split, tf32 bits
#pragma unroll
        for (int p = 0; p < 8; ++p) {
            int idx = p * 128 + t;
            int r = idx >> 4, c = (idx & 15) << 2;
            float4 kv = *(const float4*)(Kg + (size_t)(kb + r) * DD + c);
            float4 vv = *(const float4*)(Vg + (size_t)(kb + r) * DD + c);
            uint4 kh, kl, vh, vl;
            kh.x = f2tf32(kv.x); kl.x = f2tf32(kv.x - __uint_as_float(kh.x));
            kh.y = f2tf32(kv.y); kl.y = f2tf32(kv.y - __uint_as_float(kh.y));
            kh.z = f2tf32(kv.z); kl.z = f2tf32(kv.z - __uint_as_float(kh.z));
            kh.w = f2tf32(kv.w); kl.w = f2tf32(kv.w - __uint_as_float(kh.w));
            vh.x = f2tf32(vv.x); vl.x = f2tf32(vv.x - __uint_as_float(vh.x));
            vh.y = f2tf32(vv.y); vl.y = f2tf32(vv.y - __uint_as_float(vh.y));
            vh.z = f2tf32(vv.z); vl.z = f2tf32(vv.z - __uint_as_float(vh.z));
            vh.w = f2tf32(vv.w); vl.w = f2tf32(vv.w - __uint_as_float(vh.w));
            *(uint4*)&KsH[r * FP + c] = kh;
            *(uint4*)&KsL[r * FP + c] = kl;
            *(uint4*)&VsH[r * FP + c] = vh;
            *(uint4*)&VsL[r * FP + c] = vl;
        }
        __syncthreads();

        // S = (Q * scale) K^T  -- 3x tf32
        float s[8][4];
#pragma unroll
        for (int nt = 0; nt < 8; ++nt)
#pragma unroll
            for (int i = 0; i < 4; ++i) s[nt][i] = 0.f;

#pragma unroll
        for (int ks = 0; ks < 8; ++ks) {
            const int kc = ks * 8;
#pragma unroll
            for (int nt = 0; nt < 8; ++nt) {
                const int br = (nt * 8 + g) * FP + kc;
                uint32_t bh0 = KsH[br + tg], bh1 = KsH[br + tg + 4];
                uint32_t bl0 = KsL[br + tg], bl1 = KsL[br + tg + 4];
                mma_tf32(s[nt][0], s[nt][1], s[nt][2], s[nt][3],
                         qh[ks][0], qh[ks][1], qh[ks][2], qh[ks][3], bh0, bh1);
                mma_tf32(s[nt][0], s[nt][1], s[nt][2], s[nt][3],
                         ql[ks][0], ql[ks][1], ql[ks][2], ql[ks][3], bh0, bh1);
                mma_tf32(s[nt][0], s[nt][1], s[nt][2], s[nt][3],
                         qh[ks][0], qh[ks][1], qh[ks][2], qh[ks][3], bl0, bl1);
            }
        }

        // Causal mask (diagonal tile only)
        if (kt == (int)blockIdx.x) {
            const int row0 = qbase + wid * 16 + g;
#pragma unroll
            for (int nt = 0; nt < 8; ++nt) {
                const int c0 = kb + nt * 8 + 2 * tg;
                if (c0     > row0)     s[nt][0] = -CUDART_INF_F;
                if (c0 + 1 > row0)     s[nt][1] = -CUDART_INF_F;
                if (c0     > row0 + 8) s[nt][2] = -CUDART_INF_F;
                if (c0 + 1 > row0 + 8) s[nt][3] = -CUDART_INF_F;
            }
        }

        // Online softmax (exp2 domain)
        float mx0 = -CUDART_INF_F, mx1 = -CUDART_INF_F;
#pragma unroll
        for (int nt = 0; nt < 8; ++nt) {
            mx0 = fmaxf(mx0, fmaxf(s[nt][0], s[nt][1]));
            mx1 = fmaxf(mx1, fmaxf(s[nt][2], s[nt][3]));
        }
        mx0 = fmaxf(mx0, __shfl_xor_sync(0xffffffffu, mx0, 1));
        mx0 = fmaxf(mx0, __shfl_xor_sync(0xffffffffu, mx0, 2));
        mx1 = fmaxf(mx1, __shfl_xor_sync(0xffffffffu, mx1, 1));
        mx1 = fmaxf(mx1, __shfl_xor_sync(0xffffffffu, mx1, 2));

        float mn0 = fmaxf(m0, mx0), mn1 = fmaxf(m1, mx1);
        float cr0 = ex2f(m0 - mn0), cr1 = ex2f(m1 - mn1);
        float sum0 = 0.f, sum1 = 0.f;
        const int prow = (wid * 16 + g) * FP;
#pragma unroll
        for (int nt = 0; nt < 8; ++nt) {
            float p0 = ex2f(s[nt][0] - mn0), p1 = ex2f(s[nt][1] - mn0);
            float p2 = ex2f(s[nt][2] - mn1), p3 = ex2f(s[nt][3] - mn1);
            sum0 += p0 + p1;
            sum1 += p2 + p3;
            uint32_t h0 = f2tf32(p0), h1 = f2tf32(p1);
            uint32_t h2 = f2tf32(p2), h3 = f2tf32(p3);
            const int pc = nt * 8 + 2 * tg;
            *(uint2*)&PsH[prow + pc]          = make_uint2(h0, h1);
            *(uint2*)&PsH[prow + 8 * FP + pc] = make_uint2(h2, h3);
            *(uint2*)&PsL[prow + pc]          = make_uint2(
                f2tf32(p0 - __uint_as_float(h0)), f2tf32(p1 - __uint_as_float(h1)));
            *(uint2*)&PsL[prow + 8 * FP + pc] = make_uint2(
                f2tf32(p2 - __uint_as_float(h2)), f2tf32(p3 - __uint_as_float(h3)));
        }
        sum0 += __shfl_xor_sync(0xffffffffu, sum0, 1);
        sum0 += __shfl_xor_sync(0xffffffffu, sum0, 2);
        sum1 += __shfl_xor_sync(0xffffffffu, sum1, 1);
        sum1 += __shfl_xor_sync(0xffffffffu, sum1, 2);
        l0 = l0 * cr0 + sum0;
        l1 = l1 * cr1 + sum1;
        m0 = mn0; m1 = mn1;
#pragma unroll
        for (int nt = 0; nt < 8; ++nt) {
            o[nt][0] *= cr0; o[nt][1] *= cr0;
            o[nt][2] *= cr1; o[nt][3] *= cr1;
        }
        __syncwarp();

        // O += P V  -- 3x tf32
#pragma unroll
        for (int ks = 0; ks < 8; ++ks) {
            const int kc = ks * 8;
            uint32_t ah0 = PsH[prow + kc + tg];
            uint32_t ah1 = PsH[prow + 8 * FP + kc + tg];
            uint32_t ah2 = PsH[prow + kc + tg + 4];
            uint32_t ah3 = PsH[prow + 8 * FP + kc + tg + 4];
            uint32_t al0 = PsL[prow + kc + tg];
            uint32_t al1 = PsL[prow + 8 * FP + kc + tg];
            uint32_t al2 = PsL[prow + kc + tg + 4];
            uint32_t al3 = PsL[prow + 8 * FP + kc + tg + 4];
#pragma unroll
            for (int nt = 0; nt < 8; ++nt) {
                const int vb = (kc + tg) * FP + nt * 8 + g;
                uint32_t bh0 = VsH[vb], bh1 = VsH[vb + 4 * FP];
                uint32_t bl0 = VsL[vb], bl1 = VsL[vb + 4 * FP];
                mma_tf32(o[nt][0], o[nt][1], o[nt][2], o[nt][3],
                         ah0, ah1, ah2, ah3, bh0, bh1);
                mma_tf32(o[nt][0], o[nt][1], o[nt][2], o[nt][3],
                         al0, al1, al2, al3, bh0, bh1);
                mma_tf32(o[nt][0], o[nt][1], o[nt][2], o[nt][3],
                         ah0, ah1, ah2, ah3, bl0, bl1);
            }
        }
        __syncthreads();
    }

    // Epilogue
    const float i0 = 1.0f / l0, i1 = 1.0f / l1;
    const int row0 = qbase + wid * 16 + g;
#pragma unroll
    for (int nt = 0; nt < 8; ++nt) {
        const int c = nt * 8 + 2 * tg;
        *(float2*)(Og + (size_t)row0 * DD + c) =
            make_float2(o[nt][0] * i0, o[nt][1] * i0);
        *(float2*)(Og + (size_t)(row0 + 8) * DD + c) =
            make_float2(o[nt][2] * i1, o[nt][3] * i1);
    }
}

// ---------------------------------------------------------------------------
extern "C" void kernel_launch(void* const* d_in, const int* in_sizes, int n_in,
                              void* d_out, int out_size)
{
    const float* x   = (const float*)d_in[0];
    const int*   pos = (const int*)  d_in[1];
    const float* Wq  = (const float*)d_in[2];
    const float* Wk  = (const float*)d_in[3];
    const float* Wv  = (const float*)d_in[4];
    const float* Wo  = (const float*)d_in[5];
    float* out = (float*)d_out;

    float *Q, *K, *V, *Aw;
    cudaGetSymbolAddress((void**)&Q,  g_Q);
    cudaGetSymbolAddress((void**)&K,  g_K);
    cudaGetSymbolAddress((void**)&V,  g_V);
    cudaGetSymbolAddress((void**)&Aw, g_A);

    cudaFuncSetAttribute(gemm_tf32, cudaFuncAttributeMaxDynamicSharedMemorySize,
                         G_SMEM);
    cudaFuncSetAttribute(flash_mma, cudaFuncAttributeMaxDynamicSharedMemorySize,
                         F_SMEM);

    dim3 gg(DD / 128, BS_ROWS / 128);   // (8, 64)

    gemm_tf32<<<gg, 256, G_SMEM>>>(x, Wq, Q, BS_ROWS, DD, DD);
    gemm_tf32<<<gg, 256, G_SMEM>>>(x, Wk, K, BS_ROWS, DD, DD);
    gemm_tf32<<<gg, 256, G_SMEM>>>(x, Wv, V, BS_ROWS, DD, DD);

    const int rope_elems = BS_ROWS * 512;
    rope_kernel<<<rope_elems / 256, 256>>>(Q, pos);
    rope_kernel<<<rope_elems / 256, 256>>>(K, pos);

    flash_mma<<<dim3(SS / 64, HH, BB), 128, F_SMEM>>>(Q, K, V, Aw);

    gemm_tf32<<<gg, 256, G_SMEM>>>(Aw, Wo, out, BS_ROWS, DD, DD);
}

// round 12
// speedup vs baseline: 1.0442x; 1.0049x over previous
#include <cuda_runtime.h>
#include <math_constants.h>
#include <cstdint>

#define BB 4
#define SS 2048
#define DD 1024
#define HH 16
#define DKK 64
#define BS_ROWS (BB*SS)   // 8192

// Persistent scratch (allocation-free rule: __device__ globals)
__device__ float g_Q[(size_t)BS_ROWS * DD];
__device__ float g_K[(size_t)BS_ROWS * DD];
__device__ float g_V[(size_t)BS_ROWS * DD];
__device__ float g_A[(size_t)BS_ROWS * DD];

__device__ __forceinline__ uint32_t f2tf32(float x) {
    uint32_t u;
    asm("cvt.rna.tf32.f32 %0, %1;" : "=r"(u) : "f"(x));
    return u;
}

__device__ __forceinline__ float ex2f(float x) {
    float y;
    asm("ex2.approx.f32 %0, %1;" : "=f"(y) : "f"(x));
    return y;
}

__device__ __forceinline__ uint32_t smem_u32(const void* p) {
    uint32_t a;
    asm("{ .reg .u64 t; cvta.to.shared.u64 t, %1; cvt.u32.u64 %0, t; }"
        : "=r"(a) : "l"(p));
    return a;
}

__device__ __forceinline__ void ldsm_x4(uint32_t& r0, uint32_t& r1,
                                        uint32_t& r2, uint32_t& r3,
                                        uint32_t addr) {
    asm volatile("ldmatrix.sync.aligned.m8n8.x4.shared.b16 {%0,%1,%2,%3}, [%4];"
                 : "=r"(r0), "=r"(r1), "=r"(r2), "=r"(r3) : "r"(addr));
}

__device__ __forceinline__ void mma_tf32(float& c0, float& c1, float& c2, float& c3,
                                         uint32_t a0, uint32_t a1, uint32_t a2, uint32_t a3,
                                         uint32_t b0, uint32_t b1) {
    asm volatile(
        "mma.sync.aligned.m16n8k8.row.col.f32.tf32.tf32.f32 "
        "{%0,%1,%2,%3}, {%4,%5,%6,%7}, {%8,%9}, {%0,%1,%2,%3};"
        : "+f"(c0), "+f"(c1), "+f"(c2), "+f"(c3)
        : "r"(a0), "r"(a1), "r"(a2), "r"(a3), "r"(b0), "r"(b1));
}

// ===========================================================================
// Tensor-core GEMM-NT (tf32 mma.sync): C[M,N] = A[M,K] * Bw[N,K]^T
// BM=BN=128, BK=32, 256 threads (4m x 2n warps, warp tile 32x64).
// Double-buffered smem, ONE __syncthreads per K-tile. tf32 staged in smem
// (cvt once at store); ldmatrix.x4 fragment loads; LDG register-staged.
// ===========================================================================
#define BKG 32
#define GPAD 36
#define GSTAGE (128 * GPAD)               // words per stage per operand
#define G_SMEM (4 * GSTAGE * 4)           // 2 stages x (A+B) = 73728 B

__global__ __launch_bounds__(256, 2)
void gemm_tf32(const float* __restrict__ A, const float* __restrict__ Bw,
               float* __restrict__ C, int M, int N, int K)
{
    extern __shared__ uint32_t gsm[];
    uint32_t* As = gsm;                 // [2][128][GPAD]
    uint32_t* Bs = gsm + 2 * GSTAGE;    // [2][128][GPAD]

    const int t    = threadIdx.x;
    const int wid  = t >> 5;
    const int lane = t & 31;
    const int g    = lane >> 2;
    const int tg   = lane & 3;
    const int warp_m = wid & 3;
    const int warp_n = wid >> 2;

    const int rowBase = blockIdx.y * 128;
    const int colBase = blockIdx.x * 128;

    const float* Ag = A  + (size_t)rowBase * K;
    const float* Bg = Bw + (size_t)colBase * K;

    const int lr0 = t >> 3;          // 0..31
    const int lc4 = (t & 7) << 2;    // 0,4,..,28

    // ldmatrix per-lane base addresses (stage 0; add stage-byte offset at use)
    const uint32_t STB = GSTAGE * 4;   // stage bytes
    const int arow = lane & 15;
    const int acol = (lane < 16) ? 0 : 4;
    const uint32_t aBase0 =
        smem_u32(&As[(size_t)(warp_m * 32 + arow) * GPAD + acol]);
    const uint32_t aBase1 = aBase0 + 16 * GPAD * 4;

    const int brow = ((lane >> 4) << 3) + (lane & 7);
    const int bcol = (lane & 8) ? 4 : 0;
    uint32_t bBase[4];
#pragma unroll
    for (int p = 0; p < 4; ++p)
        bBase[p] = smem_u32(&Bs[(size_t)(warp_n * 64 + p * 16 + brow) * GPAD + bcol]);

    float acc[2][8][4];
#pragma unroll
    for (int mt = 0; mt < 2; ++mt)
#pragma unroll
        for (int nt = 0; nt < 8; ++nt)
#pragma unroll
            for (int i = 0; i < 4; ++i) acc[mt][nt][i] = 0.f;

    const int NIT = K / BKG;   // 32

    // Prologue: load + convert + store tile 0 into stage 0
    float4 stA[4], stB[4];
#pragma unroll
    for (int p = 0; p < 4; ++p) {
        int r = p * 32 + lr0;
        stA[p] = *(const float4*)(Ag + (size_t)r * K + lc4);
        stB[p] = *(const float4*)(Bg + (size_t)r * K + lc4);
    }
#pragma unroll
    for (int p = 0; p < 4; ++p) {
        int r = p * 32 + lr0;
        uint32_t* ad = &As[(size_t)r * GPAD + lc4];
        uint32_t* bd = &Bs[(size_t)r * GPAD + lc4];
        ad[0] = f2tf32(stA[p].x); ad[1] = f2tf32(stA[p].y);
        ad[2] = f2tf32(stA[p].z); ad[3] = f2tf32(stA[p].w);
        bd[0] = f2tf32(stB[p].x); bd[1] = f2tf32(stB[p].y);
        bd[2] = f2tf32(stB[p].z); bd[3] = f2tf32(stB[p].w);
    }
    __syncthreads();

    for (int kt = 0; kt < NIT; ++kt) {
        // Issue next tile's global loads (consumed after compute)
        if (kt + 1 < NIT) {
            const int k1 = (kt + 1) * BKG;
#pragma unroll
            for (int p = 0; p < 4; ++p) {
                int r = p * 32 + lr0;
                stA[p] = *(const float4*)(Ag + (size_t)r * K + k1 + lc4);
                stB[p] = *(const float4*)(Bg + (size_t)r * K + k1 + lc4);
            }
        }

        // Compute current tile from smem via ldmatrix
        const uint32_t cur = (uint32_t)(kt & 1) * STB;
#pragma unroll
        for (int kk = 0; kk < 4; ++kk) {
            const uint32_t ko = cur + kk * 32;
            uint32_t af0[4], af1[4];
            ldsm_x4(af0[0], af0[1], af0[2], af0[3], aBase0 + ko);
            ldsm_x4(af1[0], af1[1], af1[2], af1[3], aBase1 + ko);
#pragma unroll
            for (int p = 0; p < 4; ++p) {
                uint32_t b00, b01, b10, b11;
                ldsm_x4(b00, b01, b10, b11, bBase[p] + ko);
                mma_tf32(acc[0][2*p][0], acc[0][2*p][1], acc[0][2*p][2], acc[0][2*p][3],
                         af0[0], af0[1], af0[2], af0[3], b00, b01);
                mma_tf32(acc[1][2*p][0], acc[1][2*p][1], acc[1][2*p][2], acc[1][2*p][3],
                         af1[0], af1[1], af1[2], af1[3], b00, b01);
                mma_tf32(acc[0][2*p+1][0], acc[0][2*p+1][1], acc[0][2*p+1][2], acc[0][2*p+1][3],
                         af0[0], af0[1], af0[2], af0[3], b10, b11);
                mma_tf32(acc[1][2*p+1][0], acc[1][2*p+1][1], acc[1][2*p+1][2], acc[1][2*p+1][3],
                         af1[0], af1[1], af1[2], af1[3], b10, b11);
            }
        }

        // Convert + store next tile into the ALTERNATE stage (no barrier
        // needed before this: all reads of that stage completed before the
        // previous iteration's barrier).
        if (kt + 1 < NIT) {
            const uint32_t nso = (uint32_t)((kt + 1) & 1) * GSTAGE;
#pragma unroll
            for (int p = 0; p < 4; ++p) {
                int r = p * 32 + lr0;
                uint32_t* ad = &As[nso + (size_t)r * GPAD + lc4];
                uint32_t* bd = &Bs[nso + (size_t)r * GPAD + lc4];
                ad[0] = f2tf32(stA[p].x); ad[1] = f2tf32(stA[p].y);
                ad[2] = f2tf32(stA[p].z); ad[3] = f2tf32(stA[p].w);
                bd[0] = f2tf32(stB[p].x); bd[1] = f2tf32(stB[p].y);
                bd[2] = f2tf32(stB[p].z); bd[3] = f2tf32(stB[p].w);
            }
        }
        __syncthreads();
    }

#pragma unroll
    for (int mt = 0; mt < 2; ++mt) {
        const int r0 = rowBase + warp_m * 32 + mt * 16 + g;
#pragma unroll
        for (int nt = 0; nt < 8; ++nt) {
            const int c = colBase + warp_n * 64 + nt * 8 + tg * 2;
            *(float2*)(C + (size_t)r0 * N + c) =
                make_float2(acc[mt][nt][0], acc[mt][nt][1]);
            *(float2*)(C + (size_t)(r0 + 8) * N + c) =
                make_float2(acc[mt][nt][2], acc[mt][nt][3]);
        }
    }
}

// ---------------------------------------------------------------------------
// RoPE (in place).
// ---------------------------------------------------------------------------
__global__ void rope_kernel(float* __restrict__ q, const int* __restrict__ pos)
{
    int i = blockIdx.x * blockDim.x + threadIdx.x;
    if (i >= BS_ROWS * 512) return;
    int row = i >> 9;
    int p   = i & 511;
    int j   = p & 31;
    int s   = row & (SS - 1);
    float posv = (float)pos[s];
    float inv = expf(-(float)j * 0.28782313662425572f);
    float ang = posv * inv;
    float sn, cs;
    sincosf(ang, &sn, &cs);
    size_t base = (size_t)row * DD + (size_t)(p << 1);
    float x1 = q[base + 0];
    float x2 = q[base + 1];
    q[base + 0] = x1 * cs - x2 * sn;
    q[base + 1] = x1 * sn + x2 * cs;
}

// ===========================================================================
// Tensor-core flash attention (causal), 3x-tf32 error-compensated.
// Br=Bc=64, 128 threads (4 warps), warp owns 16 query rows.  (R6 version)
// ===========================================================================
#define FP 68
#define F_SMEM (6 * 64 * FP * 4)   // 104448 B

__global__ __launch_bounds__(128, 2)
void flash_mma(const float* __restrict__ Q, const float* __restrict__ K,
               const float* __restrict__ V, float* __restrict__ O)
{
    extern __shared__ uint32_t fsm[];
    uint32_t* KsH = fsm;
    uint32_t* KsL = KsH + 64 * FP;
    uint32_t* VsH = KsL + 64 * FP;
    uint32_t* VsL = VsH + 64 * FP;
    uint32_t* PsH = VsL + 64 * FP;
    uint32_t* PsL = PsH + 64 * FP;

    const int t    = threadIdx.x;
    const int wid  = t >> 5;
    const int lane = t & 31;
    const int g    = lane >> 2;
    const int tg   = lane & 3;
    const int qbase = blockIdx.x * 64;

    const size_t hb = (size_t)blockIdx.z * SS * DD + (size_t)blockIdx.y * DKK;
    const float* Qg = Q + hb;
    const float* Kg = K + hb;
    const float* Vg = V + hb;
    float*       Og = O + hb;

    const float QS = 0.125f * 1.4426950408889634f;   // 1/sqrt(64) * log2(e)

    // Stage Q (scaled) hi/lo into KsH/KsL, then pull fragments to registers
#pragma unroll
    for (int p = 0; p < 8; ++p) {
        int idx = p * 128 + t;
        int r = idx >> 4, c = (idx & 15) << 2;
        float4 v = *(const float4*)(Qg + (size_t)(qbase + r) * DD + c);
        float f0 = v.x * QS, f1 = v.y * QS, f2 = v.z * QS, f3 = v.w * QS;
        uint4 h, l;
        h.x = f2tf32(f0); l.x = f2tf32(f0 - __uint_as_float(h.x));
        h.y = f2tf32(f1); l.y = f2tf32(f1 - __uint_as_float(h.y));
        h.z = f2tf32(f2); l.z = f2tf32(f2 - __uint_as_float(h.z));
        h.w = f2tf32(f3); l.w = f2tf32(f3 - __uint_as_float(h.w));
        *(uint4*)&KsH[r * FP + c] = h;
        *(uint4*)&KsL[r * FP + c] = l;
    }
    __syncthreads();

    uint32_t qh[8][4], ql[8][4];
    const int arow = wid * 16 + g;
#pragma unroll
    for (int ks = 0; ks < 8; ++ks) {
        int kc = ks * 8 + tg;
        qh[ks][0] = KsH[arow * FP + kc];
        qh[ks][1] = KsH[(arow + 8) * FP + kc];
        qh[ks][2] = KsH[arow * FP + kc + 4];
        qh[ks][3] = KsH[(arow + 8) * FP + kc + 4];
        ql[ks][0] = KsL[arow * FP + kc];
        ql[ks][1] = KsL[(arow + 8) * FP + kc];
        ql[ks][2] = KsL[arow * FP + kc + 4];
        ql[ks][3] = KsL[(arow + 8) * FP + kc + 4];
    }
    __syncthreads();

    float m0 = -CUDART_INF_F, m1 = -CUDART_INF_F, l0 = 0.f, l1 = 0.f;
    float o[8][4];
#pragma unroll
    for (int nt = 0; nt < 8; ++nt)
#pragma unroll
        for (int i = 0; i < 4; ++i) o[nt][i] = 0.f;

    for (int kt = 0; kt <= (int)blockIdx.x; ++kt) {
        const int kb = kt * 64;

        // Load K, V tiles, hi/lo split, tf32 bits
#pragma unroll
        for (int p = 0; p < 8; ++p) {
            int idx = p * 128 + t;
            int r = idx >> 4, c = (idx & 15) << 2;
            float4 kv = *(const float4*)(Kg + (size_t)(kb + r) * DD + c);
            float4 vv = *(const float4*)(Vg + (size_t)(kb + r) * DD + c);
            uint4 kh, kl, vh, vl;
            kh.x = f2tf32(kv.x); kl.x = f2tf32(kv.x - __uint_as_float(kh.x));
            kh.y = f2tf32(kv.y); kl.y = f2tf32(kv.y - __uint_as_float(kh.y));
            kh.z = f2tf32(kv.z); kl.z = f2tf32(kv.z - __uint_as_float(kh.z));
            kh.w = f2tf32(kv.w); kl.w = f2tf32(kv.w - __uint_as_float(kh.w));
            vh.x = f2tf32(vv.x); vl.x = f2tf32(vv.x - __uint_as_float(vh.x));
            vh.y = f2tf32(vv.y); vl.y = f2tf32(vv.y - __uint_as_float(vh.y));
            vh.z = f2tf32(vv.z); vl.z = f2tf32(vv.z - __uint_as_float(vh.z));
            vh.w = f2tf32(vv.w); vl.w = f2tf32(vv.w - __uint_as_float(vh.w));
            *(uint4*)&KsH[r * FP + c] = kh;
            *(uint4*)&KsL[r * FP + c] = kl;
            *(uint4*)&VsH[r * FP + c] = vh;
            *(uint4*)&VsL[r * FP + c] = vl;
        }
        __syncthreads();

        // S = (Q * scale) K^T  -- 3x tf32
        float s[8][4];
#pragma unroll
        for (int nt = 0; nt < 8; ++nt)
#pragma unroll
            for (int i = 0; i < 4; ++i) s[nt][i] = 0.f;

#pragma unroll
        for (int ks = 0; ks < 8; ++ks) {
            const int kc = ks * 8;
#pragma unroll
            for (int nt = 0; nt < 8; ++nt) {
                const int br = (nt * 8 + g) * FP + kc;
                uint32_t bh0 = KsH[br + tg], bh1 = KsH[br + tg + 4];
                uint32_t bl0 = KsL[br + tg], bl1 = KsL[br + tg + 4];
                mma_tf32(s[nt][0], s[nt][1], s[nt][2], s[nt][3],
                         qh[ks][0], qh[ks][1], qh[ks][2], qh[ks][3], bh0, bh1);
                mma_tf32(s[nt][0], s[nt][1], s[nt][2], s[nt][3],
                         ql[ks][0], ql[ks][1], ql[ks][2], ql[ks][3], bh0, bh1);
                mma_tf32(s[nt][0], s[nt][1], s[nt][2], s[nt][3],
                         qh[ks][0], qh[ks][1], qh[ks][2], qh[ks][3], bl0, bl1);
            }
        }

        // Causal mask (diagonal tile only)
        if (kt == (int)blockIdx.x) {
            const int row0 = qbase + wid * 16 + g;
#pragma unroll
            for (int nt = 0; nt < 8; ++nt) {
                const int c0 = kb + nt * 8 + 2 * tg;
                if (c0     > row0)     s[nt][0] = -CUDART_INF_F;
                if (c0 + 1 > row0)     s[nt][1] = -CUDART_INF_F;
                if (c0     > row0 + 8) s[nt][2] = -CUDART_INF_F;
                if (c0 + 1 > row0 + 8) s[nt][3] = -CUDART_INF_F;
            }
        }

        // Online softmax (exp2 domain)
        float mx0 = -CUDART_INF_F, mx1 = -CUDART_INF_F;
#pragma unroll
        for (int nt = 0; nt < 8; ++nt) {
            mx0 = fmaxf(mx0, fmaxf(s[nt][0], s[nt][1]));
            mx1 = fmaxf(mx1, fmaxf(s[nt][2], s[nt][3]));
        }
        mx0 = fmaxf(mx0, __shfl_xor_sync(0xffffffffu, mx0, 1));
        mx0 = fmaxf(mx0, __shfl_xor_sync(0xffffffffu, mx0, 2));
        mx1 = fmaxf(mx1, __shfl_xor_sync(0xffffffffu, mx1, 1));
        mx1 = fmaxf(mx1, __shfl_xor_sync(0xffffffffu, mx1, 2));

        float mn0 = fmaxf(m0, mx0), mn1 = fmaxf(m1, mx1);
        float cr0 = ex2f(m0 - mn0), cr1 = ex2f(m1 - mn1);
        float sum0 = 0.f, sum1 = 0.f;
        const int prow = (wid * 16 + g) * FP;
#pragma unroll
        for (int nt = 0; nt < 8; ++nt) {
            float p0 = ex2f(s[nt][0] - mn0), p1 = ex2f(s[nt][1] - mn0);
            float p2 = ex2f(s[nt][2] - mn1), p3 = ex2f(s[nt][3] - mn1);
            sum0 += p0 + p1;
            sum1 += p2 + p3;
            uint32_t h0 = f2tf32(p0), h1 = f2tf32(p1);
            uint32_t h2 = f2tf32(p2), h3 = f2tf32(p3);
            const int pc = nt * 8 + 2 * tg;
            *(uint2*)&PsH[prow + pc]          = make_uint2(h0, h1);
            *(uint2*)&PsH[prow + 8 * FP + pc] = make_uint2(h2, h3);
            *(uint2*)&PsL[prow + pc]          = make_uint2(
                f2tf32(p0 - __uint_as_float(h0)), f2tf32(p1 - __uint_as_float(h1)));
            *(uint2*)&PsL[prow + 8 * FP + pc] = make_uint2(
                f2tf32(p2 - __uint_as_float(h2)), f2tf32(p3 - __uint_as_float(h3)));
        }
        sum0 += __shfl_xor_sync(0xffffffffu, sum0, 1);
        sum0 += __shfl_xor_sync(0xffffffffu, sum0, 2);
        sum1 += __shfl_xor_sync(0xffffffffu, sum1, 1);
        sum1 += __shfl_xor_sync(0xffffffffu, sum1, 2);
        l0 = l0 * cr0 + sum0;
        l1 = l1 * cr1 + sum1;
        m0 = mn0; m1 = mn1;
#pragma unroll
        for (int nt = 0; nt < 8; ++nt) {
            o[nt][0] *= cr0; o[nt][1] *= cr0;
            o[nt][2] *= cr1; o[nt][3] *= cr1;
        }
        __syncwarp();

        // O += P V  -- 3x tf32
#pragma unroll
        for (int ks = 0; ks < 8; ++ks) {
            const int kc = ks * 8;
            uint32_t ah0 = PsH[prow + kc + tg];
            uint32_t ah1 = PsH[prow + 8 * FP + kc + tg];
            uint32_t ah2 = PsH[prow + kc + tg + 4];
            uint32_t ah3 = PsH[prow + 8 * FP + kc + tg + 4];
            uint32_t al0 = PsL[prow + kc + tg];
            uint32_t al1 = PsL[prow + 8 * FP + kc + tg];
            uint32_t al2 = PsL[prow + kc + tg + 4];
            uint32_t al3 = PsL[prow + 8 * FP + kc + tg + 4];
#pragma unroll
            for (int nt = 0; nt < 8; ++nt) {
                const int vb = (kc + tg) * FP + nt * 8 + g;
                uint32_t bh0 = VsH[vb], bh1 = VsH[vb + 4 * FP];
                uint32_t bl0 = VsL[vb], bl1 = VsL[vb + 4 * FP];
                mma_tf32(o[nt][0], o[nt][1], o[nt][2], o[nt][3],
                         ah0, ah1, ah2, ah3, bh0, bh1);
                mma_tf32(o[nt][0], o[nt][1], o[nt][2], o[nt][3],
                         al0, al1, al2, al3, bh0, bh1);
                mma_tf32(o[nt][0], o[nt][1], o[nt][2], o[nt][3],
                         ah0, ah1, ah2, ah3, bl0, bl1);
            }
        }
        __syncthreads();
    }

    // Epilogue
    const float i0 = 1.0f / l0, i1 = 1.0f / l1;
    const int row0 = qbase + wid * 16 + g;
#pragma unroll
    for (int nt = 0; nt < 8; ++nt) {
        const int c = nt * 8 + 2 * tg;
        *(float2*)(Og + (size_t)row0 * DD + c) =
            make_float2(o[nt][0] * i0, o[nt][1] * i0);
        *(float2*)(Og + (size_t)(row0 + 8) * DD + c) =
            make_float2(o[nt][2] * i1, o[nt][3] * i1);
    }
}

// ---------------------------------------------------------------------------
extern "C" void kernel_launch(void* const* d_in, const int* in_sizes, int n_in,
                              void* d_out, int out_size)
{
    const float* x   = (const float*)d_in[0];
    const int*   pos = (const int*)  d_in[1];
    const float* Wq  = (const float*)d_in[2];
    const float* Wk  = (const float*)d_in[3];
    const float* Wv  = (const float*)d_in[4];
    const float* Wo  = (const float*)d_in[5];
    float* out = (float*)d_out;

    float *Q, *K, *V, *Aw;
    cudaGetSymbolAddress((void**)&Q,  g_Q);
    cudaGetSymbolAddress((void**)&K,  g_K);
    cudaGetSymbolAddress((void**)&V,  g_V);
    cudaGetSymbolAddress((void**)&Aw, g_A);

    cudaFuncSetAttribute(gemm_tf32, cudaFuncAttributeMaxDynamicSharedMemorySize,
                         G_SMEM);
    cudaFuncSetAttribute(flash_mma, cudaFuncAttributeMaxDynamicSharedMemorySize,
                         F_SMEM);

    dim3 gg(DD / 128, BS_ROWS / 128);   // (8, 64)

    gemm_tf32<<<gg, 256, G_SMEM>>>(x, Wq, Q, BS_ROWS, DD, DD);
    gemm_tf32<<<gg, 256, G_SMEM>>>(x, Wk, K, BS_ROWS, DD, DD);
    gemm_tf32<<<gg, 256, G_SMEM>>>(x, Wv, V, BS_ROWS, DD, DD);

    const int rope_elems = BS_ROWS * 512;
    rope_kernel<<<rope_elems / 256, 256>>>(Q, pos);
    rope_kernel<<<rope_elems / 256, 256>>>(K, pos);

    flash_mma<<<dim3(SS / 64, HH, BB), 128, F_SMEM>>>(Q, K, V, Aw);

    gemm_tf32<<<gg, 256, G_SMEM>>>(Aw, Wo, out, BS_ROWS, DD, DD);
}

// round 13
// speedup vs baseline: 1.1516x; 1.1028x over previous
#include <cuda_runtime.h>
#include <math_constants.h>
#include <cstdint>

#define BB 4
#define SS 2048
#define DD 1024
#define HH 16
#define DKK 64
#define BS_ROWS (BB*SS)   // 8192

// Persistent scratch (allocation-free rule: __device__ globals)
__device__ float g_Q[(size_t)BS_ROWS * DD];
__device__ float g_K[(size_t)BS_ROWS * DD];
__device__ float g_V[(size_t)BS_ROWS * DD];
__device__ float g_A[(size_t)BS_ROWS * DD];

__device__ __forceinline__ uint32_t f2tf32(float x) {
    uint32_t u;
    asm("cvt.rna.tf32.f32 %0, %1;" : "=r"(u) : "f"(x));
    return u;
}

__device__ __forceinline__ float ex2f(float x) {
    float y;
    asm("ex2.approx.f32 %0, %1;" : "=f"(y) : "f"(x));
    return y;
}

__device__ __forceinline__ uint32_t smem_u32(const void* p) {
    uint32_t a;
    asm("{ .reg .u64 t; cvta.to.shared.u64 t, %1; cvt.u32.u64 %0, t; }"
        : "=r"(a) : "l"(p));
    return a;
}

__device__ __forceinline__ void ldsm_x4(uint32_t& r0, uint32_t& r1,
                                        uint32_t& r2, uint32_t& r3,
                                        uint32_t addr) {
    asm volatile("ldmatrix.sync.aligned.m8n8.x4.shared.b16 {%0,%1,%2,%3}, [%4];"
                 : "=r"(r0), "=r"(r1), "=r"(r2), "=r"(r3) : "r"(addr));
}

__device__ __forceinline__ void mma_tf32(float& c0, float& c1, float& c2, float& c3,
                                         uint32_t a0, uint32_t a1, uint32_t a2, uint32_t a3,
                                         uint32_t b0, uint32_t b1) {
    asm volatile(
        "mma.sync.aligned.m16n8k8.row.col.f32.tf32.tf32.f32 "
        "{%0,%1,%2,%3}, {%4,%5,%6,%7}, {%8,%9}, {%0,%1,%2,%3};"
        : "+f"(c0), "+f"(c1), "+f"(c2), "+f"(c3)
        : "r"(a0), "r"(a1), "r"(a2), "r"(a3), "r"(b0), "r"(b1));
}

// ===========================================================================
// Shared GEMM mainloop machinery (tf32 mma.sync, double-buffered smem,
// one barrier per K-tile, ldmatrix.x4 fragments, register-staged LDG).
// BM=BN=128, BK=32, 256 threads (4m x 2n warps, warp tile 32x64).
// ===========================================================================
#define BKG 32
#define GPAD 36
#define GSTAGE (128 * GPAD)               // words per stage per operand
#define G_SMEM (4 * GSTAGE * 4)           // 2 stages x (A+B) = 73728 B

// Mainloop producing acc[2][8][4] for a 128x128 C tile. Declared as a macro
// body via inline function to share between the two GEMM kernels.
__device__ __forceinline__ void gemm_mainloop(
    const float* __restrict__ Ag, const float* __restrict__ Bg,
    uint32_t* As, uint32_t* Bs,
    int t, int warp_m, int warp_n, float acc[2][8][4])
{
    const int lane = t & 31;
    const int lr0 = t >> 3;
    const int lc4 = (t & 7) << 2;

    const uint32_t STB = GSTAGE * 4;
    const int arow = lane & 15;
    const int acol = (lane < 16) ? 0 : 4;
    const uint32_t aBase0 =
        smem_u32(&As[(size_t)(warp_m * 32 + arow) * GPAD + acol]);
    const uint32_t aBase1 = aBase0 + 16 * GPAD * 4;

    const int brow = ((lane >> 4) << 3) + (lane & 7);
    const int bcol = (lane & 8) ? 4 : 0;
    uint32_t bBase[4];
#pragma unroll
    for (int p = 0; p < 4; ++p)
        bBase[p] = smem_u32(&Bs[(size_t)(warp_n * 64 + p * 16 + brow) * GPAD + bcol]);

    const int NIT = DD / BKG;   // 32

    float4 stA[4], stB[4];
#pragma unroll
    for (int p = 0; p < 4; ++p) {
        int r = p * 32 + lr0;
        stA[p] = *(const float4*)(Ag + (size_t)r * DD + lc4);
        stB[p] = *(const float4*)(Bg + (size_t)r * DD + lc4);
    }
#pragma unroll
    for (int p = 0; p < 4; ++p) {
        int r = p * 32 + lr0;
        uint32_t* ad = &As[(size_t)r * GPAD + lc4];
        uint32_t* bd = &Bs[(size_t)r * GPAD + lc4];
        ad[0] = f2tf32(stA[p].x); ad[1] = f2tf32(stA[p].y);
        ad[2] = f2tf32(stA[p].z); ad[3] = f2tf32(stA[p].w);
        bd[0] = f2tf32(stB[p].x); bd[1] = f2tf32(stB[p].y);
        bd[2] = f2tf32(stB[p].z); bd[3] = f2tf32(stB[p].w);
    }
    __syncthreads();

    for (int kt = 0; kt < NIT; ++kt) {
        if (kt + 1 < NIT) {
            const int k1 = (kt + 1) * BKG;
#pragma unroll
            for (int p = 0; p < 4; ++p) {
                int r = p * 32 + lr0;
                stA[p] = *(const float4*)(Ag + (size_t)r * DD + k1 + lc4);
                stB[p] = *(const float4*)(Bg + (size_t)r * DD + k1 + lc4);
            }
        }

        const uint32_t cur = (uint32_t)(kt & 1) * STB;
#pragma unroll
        for (int kk = 0; kk < 4; ++kk) {
            const uint32_t ko = cur + kk * 32;
            uint32_t af0[4], af1[4];
            ldsm_x4(af0[0], af0[1], af0[2], af0[3], aBase0 + ko);
            ldsm_x4(af1[0], af1[1], af1[2], af1[3], aBase1 + ko);
#pragma unroll
            for (int p = 0; p < 4; ++p) {
                uint32_t b00, b01, b10, b11;
                ldsm_x4(b00, b01, b10, b11, bBase[p] + ko);
                mma_tf32(acc[0][2*p][0], acc[0][2*p][1], acc[0][2*p][2], acc[0][2*p][3],
                         af0[0], af0[1], af0[2], af0[3], b00, b01);
                mma_tf32(acc[1][2*p][0], acc[1][2*p][1], acc[1][2*p][2], acc[1][2*p][3],
                         af1[0], af1[1], af1[2], af1[3], b00, b01);
                mma_tf32(acc[0][2*p+1][0], acc[0][2*p+1][1], acc[0][2*p+1][2], acc[0][2*p+1][3],
                         af0[0], af0[1], af0[2], af0[3], b10, b11);
                mma_tf32(acc[1][2*p+1][0], acc[1][2*p+1][1], acc[1][2*p+1][2], acc[1][2*p+1][3],
                         af1[0], af1[1], af1[2], af1[3], b10, b11);
            }
        }

        if (kt + 1 < NIT) {
            const uint32_t nso = (uint32_t)((kt + 1) & 1) * GSTAGE;
#pragma unroll
            for (int p = 0; p < 4; ++p) {
                int r = p * 32 + lr0;
                uint32_t* ad = &As[nso + (size_t)r * GPAD + lc4];
                uint32_t* bd = &Bs[nso + (size_t)r * GPAD + lc4];
                ad[0] = f2tf32(stA[p].x); ad[1] = f2tf32(stA[p].y);
                ad[2] = f2tf32(stA[p].z); ad[3] = f2tf32(stA[p].w);
                bd[0] = f2tf32(stB[p].x); bd[1] = f2tf32(stB[p].y);
                bd[2] = f2tf32(stB[p].z); bd[3] = f2tf32(stB[p].w);
            }
        }
        __syncthreads();
    }
}

// ---------------------------------------------------------------------------
// Plain GEMM-NT (used for the output projection).
// ---------------------------------------------------------------------------
__global__ __launch_bounds__(256, 2)
void gemm_tf32(const float* __restrict__ A, const float* __restrict__ Bw,
               float* __restrict__ C)
{
    extern __shared__ uint32_t gsm[];
    uint32_t* As = gsm;
    uint32_t* Bs = gsm + 2 * GSTAGE;

    const int t    = threadIdx.x;
    const int wid  = t >> 5;
    const int lane = t & 31;
    const int g    = lane >> 2;
    const int tg   = lane & 3;
    const int warp_m = wid & 3;
    const int warp_n = wid >> 2;

    const int rowBase = blockIdx.y * 128;
    const int colBase = blockIdx.x * 128;

    float acc[2][8][4];
#pragma unroll
    for (int mt = 0; mt < 2; ++mt)
#pragma unroll
        for (int nt = 0; nt < 8; ++nt)
#pragma unroll
            for (int i = 0; i < 4; ++i) acc[mt][nt][i] = 0.f;

    gemm_mainloop(A + (size_t)rowBase * DD, Bw + (size_t)colBase * DD,
                  As, Bs, t, warp_m, warp_n, acc);

#pragma unroll
    for (int mt = 0; mt < 2; ++mt) {
        const int r0 = rowBase + warp_m * 32 + mt * 16 + g;
#pragma unroll
        for (int nt = 0; nt < 8; ++nt) {
            const int c = colBase + warp_n * 64 + nt * 8 + tg * 2;
            *(float2*)(C + (size_t)r0 * DD + c) =
                make_float2(acc[mt][nt][0], acc[mt][nt][1]);
            *(float2*)(C + (size_t)(r0 + 8) * DD + c) =
                make_float2(acc[mt][nt][2], acc[mt][nt][3]);
        }
    }
}

// ---------------------------------------------------------------------------
// Fused QKV GEMM with RoPE epilogue on Q and K.
// grid (24, 64): blockIdx.x>>3 selects {Wq->Q, Wk->K, Wv->V}.
// ---------------------------------------------------------------------------
__global__ __launch_bounds__(256, 2)
void gemm_qkv(const float* __restrict__ x,
              const float* __restrict__ Wq, const float* __restrict__ Wk,
              const float* __restrict__ Wv, const int* __restrict__ pos,
              float* __restrict__ Q, float* __restrict__ K,
              float* __restrict__ V)
{
    extern __shared__ uint32_t gsm[];
    uint32_t* As = gsm;
    uint32_t* Bs = gsm + 2 * GSTAGE;

    const int t    = threadIdx.x;
    const int wid  = t >> 5;
    const int lane = t & 31;
    const int g    = lane >> 2;
    const int tg   = lane & 3;
    const int warp_m = wid & 3;
    const int warp_n = wid >> 2;

    const int sel = blockIdx.x >> 3;
    const float* Bw = (sel == 0) ? Wq : (sel == 1) ? Wk : Wv;
    float*       C  = (sel == 0) ? Q  : (sel == 1) ? K  : V;

    const int rowBase = blockIdx.y * 128;
    const int colBase = (blockIdx.x & 7) * 128;

    float acc[2][8][4];
#pragma unroll
    for (int mt = 0; mt < 2; ++mt)
#pragma unroll
        for (int nt = 0; nt < 8; ++nt)
#pragma unroll
            for (int i = 0; i < 4; ++i) acc[mt][nt][i] = 0.f;

    gemm_mainloop(x + (size_t)rowBase * DD, Bw + (size_t)colBase * DD,
                  As, Bs, t, warp_m, warp_n, acc);

    if (sel < 2) {
        // RoPE epilogue (Q, K): store pair (c, c+1) is the rope pair.
#pragma unroll
        for (int mt = 0; mt < 2; ++mt) {
            const int r0 = rowBase + warp_m * 32 + mt * 16 + g;
            const float p0 = (float)pos[r0 & (SS - 1)];
            const float p1 = (float)pos[(r0 + 8) & (SS - 1)];
#pragma unroll
            for (int nt = 0; nt < 8; ++nt) {
                const int c = colBase + warp_n * 64 + nt * 8 + tg * 2;
                const int j = (c & 63) >> 1;
                const float inv = expf(-(float)j * 0.28782313662425572f);
                float sn0, cs0, sn1, cs1;
                sincosf(p0 * inv, &sn0, &cs0);
                sincosf(p1 * inv, &sn1, &cs1);
                float x1 = acc[mt][nt][0], x2 = acc[mt][nt][1];
                *(float2*)(C + (size_t)r0 * DD + c) =
                    make_float2(x1 * cs0 - x2 * sn0, x1 * sn0 + x2 * cs0);
                x1 = acc[mt][nt][2]; x2 = acc[mt][nt][3];
                *(float2*)(C + (size_t)(r0 + 8) * DD + c) =
                    make_float2(x1 * cs1 - x2 * sn1, x1 * sn1 + x2 * cs1);
            }
        }
    } else {
#pragma unroll
        for (int mt = 0; mt < 2; ++mt) {
            const int r0 = rowBase + warp_m * 32 + mt * 16 + g;
#pragma unroll
            for (int nt = 0; nt < 8; ++nt) {
                const int c = colBase + warp_n * 64 + nt * 8 + tg * 2;
                *(float2*)(C + (size_t)r0 * DD + c) =
                    make_float2(acc[mt][nt][0], acc[mt][nt][1]);
                *(float2*)(C + (size_t)(r0 + 8) * DD + c) =
                    make_float2(acc[mt][nt][2], acc[mt][nt][3]);
            }
        }
    }
}

// ===========================================================================
// Tensor-core flash attention (causal), 3x-tf32 error-compensated.
// Br=Bc=64, 128 threads (4 warps), warp owns 16 query rows.
// ===========================================================================
#define FP 68
#define F_SMEM (6 * 64 * FP * 4)   // 104448 B

__global__ __launch_bounds__(128, 2)
void flash_mma(const float* __restrict__ Q, const float* __restrict__ K,
               const float* __restrict__ V, float* __restrict__ O)
{
    extern __shared__ uint32_t fsm[];
    uint32_t* KsH = fsm;
    uint32_t* KsL = KsH + 64 * FP;
    uint32_t* VsH = KsL + 64 * FP;
    uint32_t* VsL = VsH + 64 * FP;
    uint32_t* PsH = VsL + 64 * FP;
    uint32_t* PsL = PsH + 64 * FP;

    const int t    = threadIdx.x;
    const int wid  = t >> 5;
    const int lane = t & 31;
    const int g    = lane >> 2;
    const int tg   = lane & 3;
    const int qbase = blockIdx.x * 64;

    const size_t hb = (size_t)blockIdx.z * SS * DD + (size_t)blockIdx.y * DKK;
    const float* Qg = Q + hb;
    const float* Kg = K + hb;
    const float* Vg = V + hb;
    float*       Og = O + hb;

    const float QS = 0.125f * 1.4426950408889634f;   // 1/sqrt(64) * log2(e)

#pragma unroll
    for (int p = 0; p < 8; ++p) {
        int idx = p * 128 + t;
        int r = idx >> 4, c = (idx & 15) << 2;
        float4 v = *(const float4*)(Qg + (size_t)(qbase + r) * DD + c);
        float f0 = v.x * QS, f1 = v.y * QS, f2 = v.z * QS, f3 = v.w * QS;
        uint4 h, l;
        h.x = f2tf32(f0); l.x = f2tf32(f0 - __uint_as_float(h.x));
        h.y = f2tf32(f1); l.y = f2tf32(f1 - __uint_as_float(h.y));
        h.z = f2tf32(f2); l.z = f2tf32(f2 - __uint_as_float(h.z));
        h.w = f2tf32(f3); l.w = f2tf32(f3 - __uint_as_float(h.w));
        *(uint4*)&KsH[r * FP + c] = h;
        *(uint4*)&KsL[r * FP + c] = l;
    }
    __syncthreads();

    uint32_t qh[8][4], ql[8][4];
    const int arow = wid * 16 + g;
#pragma unroll
    for (int ks = 0; ks < 8; ++ks) {
        int kc = ks * 8 + tg;
        qh[ks][0] = KsH[arow * FP + kc];
        qh[ks][1] = KsH[(arow + 8) * FP + kc];
        qh[ks][2] = KsH[arow * FP + kc + 4];
        qh[ks][3] = KsH[(arow + 8) * FP + kc + 4];
        ql[ks][0] = KsL[arow * FP + kc];
        ql[ks][1] = KsL[(arow + 8) * FP + kc];
        ql[ks][2] = KsL[arow * FP + kc + 4];
        ql[ks][3] = KsL[(arow + 8) * FP + kc + 4];
    }
    __syncthreads();

    float m0 = -CUDART_INF_F, m1 = -CUDART_INF_F, l0 = 0.f, l1 = 0.f;
    float o[8][4];
#pragma unroll
    for (int nt = 0; nt < 8; ++nt)
#pragma unroll
        for (int i = 0; i < 4; ++i) o[nt][i] = 0.f;

    for (int kt = 0; kt <= (int)blockIdx.x; ++kt) {
        const int kb = kt * 64;

#pragma unroll
        for (int p = 0; p < 8; ++p) {
            int idx = p * 128 + t;
            int r = idx >> 4, c = (idx & 15) << 2;
            float4 kv = *(const float4*)(Kg + (size_t)(kb + r) * DD + c);
            float4 vv = *(const float4*)(Vg + (size_t)(kb + r) * DD + c);
            uint4 kh, kl, vh, vl;
            kh.x = f2tf32(kv.x); kl.x = f2tf32(kv.x - __uint_as_float(kh.x));
            kh.y = f2tf32(kv.y); kl.y = f2tf32(kv.y - __uint_as_float(kh.y));
            kh.z = f2tf32(kv.z); kl.z = f2tf32(kv.z - __uint_as_float(kh.z));
            kh.w = f2tf32(kv.w); kl.w = f2tf32(kv.w - __uint_as_float(kh.w));
            vh.x = f2tf32(vv.x); vl.x = f2tf32(vv.x - __uint_as_float(vh.x));
            vh.y = f2tf32(vv.y); vl.y = f2tf32(vv.y - __uint_as_float(vh.y));
            vh.z = f2tf32(vv.z); vl.z = f2tf32(vv.z - __uint_as_float(vh.z));
            vh.w = f2tf32(vv.w); vl.w = f2tf32(vv.w - __uint_as_float(vh.w));
            *(uint4*)&KsH[r * FP + c] = kh;
            *(uint4*)&KsL[r * FP + c] = kl;
            *(uint4*)&VsH[r * FP + c] = vh;
            *(uint4*)&VsL[r * FP + c] = vl;
        }
        __syncthreads();

        float s[8][4];
#pragma unroll
        for (int nt = 0; nt < 8; ++nt)
#pragma unroll
            for (int i = 0; i < 4; ++i) s[nt][i] = 0.f;

#pragma unroll
        for (int ks = 0; ks < 8; ++ks) {
            const int kc = ks * 8;
#pragma unroll
            for (int nt = 0; nt < 8; ++nt) {
                const int br = (nt * 8 + g) * FP + kc;
                uint32_t bh0 = KsH[br + tg], bh1 = KsH[br + tg + 4];
                uint32_t bl0 = KsL[br + tg], bl1 = KsL[br + tg + 4];
                mma_tf32(s[nt][0], s[nt][1], s[nt][2], s[nt][3],
                         qh[ks][0], qh[ks][1], qh[ks][2], qh[ks][3], bh0, bh1);
                mma_tf32(s[nt][0], s[nt][1], s[nt][2], s[nt][3],
                         ql[ks][0], ql[ks][1], ql[ks][2], ql[ks][3], bh0, bh1);
                mma_tf32(s[nt][0], s[nt][1], s[nt][2], s[nt][3],
                         qh[ks][0], qh[ks][1], qh[ks][2], qh[ks][3], bl0, bl1);
            }
        }

        if (kt == (int)blockIdx.x) {
            const int row0 = qbase + wid * 16 + g;
#pragma unroll
            for (int nt = 0; nt < 8; ++nt) {
                const int c0 = kb + nt * 8 + 2 * tg;
                if (c0     > row0)     s[nt][0] = -CUDART_INF_F;
                if (c0 + 1 > row0)     s[nt][1] = -CUDART_INF_F;
                if (c0     > row0 + 8) s[nt][2] = -CUDART_INF_F;
                if (c0 + 1 > row0 + 8) s[nt][3] = -CUDART_INF_F;
            }
        }

        float mx0 = -CUDART_INF_F, mx1 = -CUDART_INF_F;
#pragma unroll
        for (int nt = 0; nt < 8; ++nt) {
            mx0 = fmaxf(mx0, fmaxf(s[nt][0], s[nt][1]));
            mx1 = fmaxf(mx1, fmaxf(s[nt][2], s[nt][3]));
        }
        mx0 = fmaxf(mx0, __shfl_xor_sync(0xffffffffu, mx0, 1));
        mx0 = fmaxf(mx0, __shfl_xor_sync(0xffffffffu, mx0, 2));
        mx1 = fmaxf(mx1, __shfl_xor_sync(0xffffffffu, mx1, 1));
        mx1 = fmaxf(mx1, __shfl_xor_sync(0xffffffffu, mx1, 2));

        float mn0 = fmaxf(m0, mx0), mn1 = fmaxf(m1, mx1);
        float cr0 = ex2f(m0 - mn0), cr1 = ex2f(m1 - mn1);
        float sum0 = 0.f, sum1 = 0.f;
        const int prow = (wid * 16 + g) * FP;
#pragma unroll
        for (int nt = 0; nt < 8; ++nt) {
            float p0 = ex2f(s[nt][0] - mn0), p1 = ex2f(s[nt][1] - mn0);
            float p2 = ex2f(s[nt][2] - mn1), p3 = ex2f(s[nt][3] - mn1);
            sum0 += p0 + p1;
            sum1 += p2 + p3;
            uint32_t h0 = f2tf32(p0), h1 = f2tf32(p1);
            uint32_t h2 = f2tf32(p2), h3 = f2tf32(p3);
            const int pc = nt * 8 + 2 * tg;
            *(uint2*)&PsH[prow + pc]          = make_uint2(h0, h1);
            *(uint2*)&PsH[prow + 8 * FP + pc] = make_uint2(h2, h3);
            *(uint2*)&PsL[prow + pc]          = make_uint2(
                f2tf32(p0 - __uint_as_float(h0)), f2tf32(p1 - __uint_as_float(h1)));
            *(uint2*)&PsL[prow + 8 * FP + pc] = make_uint2(
                f2tf32(p2 - __uint_as_float(h2)), f2tf32(p3 - __uint_as_float(h3)));
        }
        sum0 += __shfl_xor_sync(0xffffffffu, sum0, 1);
        sum0 += __shfl_xor_sync(0xffffffffu, sum0, 2);
        sum1 += __shfl_xor_sync(0xffffffffu, sum1, 1);
        sum1 += __shfl_xor_sync(0xffffffffu, sum1, 2);
        l0 = l0 * cr0 + sum0;
        l1 = l1 * cr1 + sum1;
        m0 = mn0; m1 = mn1;
#pragma unroll
        for (int nt = 0; nt < 8; ++nt) {
            o[nt][0] *= cr0; o[nt][1] *= cr0;
            o[nt][2] *= cr1; o[nt][3] *= cr1;
        }
        __syncwarp();

#pragma unroll
        for (int ks = 0; ks < 8; ++ks) {
            const int kc = ks * 8;
            uint32_t ah0 = PsH[prow + kc + tg];
            uint32_t ah1 = PsH[prow + 8 * FP + kc + tg];
            uint32_t ah2 = PsH[prow + kc + tg + 4];
            uint32_t ah3 = PsH[prow + 8 * FP + kc + tg + 4];
            uint32_t al0 = PsL[prow + kc + tg];
            uint32_t al1 = PsL[prow + 8 * FP + kc + tg];
            uint32_t al2 = PsL[prow + kc + tg + 4];
            uint32_t al3 = PsL[prow + 8 * FP + kc + tg + 4];
#pragma unroll
            for (int nt = 0; nt < 8; ++nt) {
                const int vb = (kc + tg) * FP + nt * 8 + g;
                uint32_t bh0 = VsH[vb], bh1 = VsH[vb + 4 * FP];
                uint32_t bl0 = VsL[vb], bl1 = VsL[vb + 4 * FP];
                mma_tf32(o[nt][0], o[nt][1], o[nt][2], o[nt][3],
                         ah0, ah1, ah2, ah3, bh0, bh1);
                mma_tf32(o[nt][0], o[nt][1], o[nt][2], o[nt][3],
                         al0, al1, al2, al3, bh0, bh1);
                mma_tf32(o[nt][0], o[nt][1], o[nt][2], o[nt][3],
                         ah0, ah1, ah2, ah3, bl0, bl1);
            }
        }
        __syncthreads();
    }

    const float i0 = 1.0f / l0, i1 = 1.0f / l1;
    const int row0 = qbase + wid * 16 + g;
#pragma unroll
    for (int nt = 0; nt < 8; ++nt) {
        const int c = nt * 8 + 2 * tg;
        *(float2*)(Og + (size_t)row0 * DD + c) =
            make_float2(o[nt][0] * i0, o[nt][1] * i0);
        *(float2*)(Og + (size_t)(row0 + 8) * DD + c) =
            make_float2(o[nt][2] * i1, o[nt][3] * i1);
    }
}

// ---------------------------------------------------------------------------
extern "C" void kernel_launch(void* const* d_in, const int* in_sizes, int n_in,
                              void* d_out, int out_size)
{
    const float* x   = (const float*)d_in[0];
    const int*   pos = (const int*)  d_in[1];
    const float* Wq  = (const float*)d_in[2];
    const float* Wk  = (const float*)d_in[3];
    const float* Wv  = (const float*)d_in[4];
    const float* Wo  = (const float*)d_in[5];
    float* out = (float*)d_out;

    float *Q, *K, *V, *Aw;
    cudaGetSymbolAddress((void**)&Q,  g_Q);
    cudaGetSymbolAddress((void**)&K,  g_K);
    cudaGetSymbolAddress((void**)&V,  g_V);
    cudaGetSymbolAddress((void**)&Aw, g_A);

    cudaFuncSetAttribute(gemm_tf32, cudaFuncAttributeMaxDynamicSharedMemorySize,
                         G_SMEM);
    cudaFuncSetAttribute(gemm_qkv, cudaFuncAttributeMaxDynamicSharedMemorySize,
                         G_SMEM);
    cudaFuncSetAttribute(flash_mma, cudaFuncAttributeMaxDynamicSharedMemorySize,
                         F_SMEM);

    // Fused QKV projection + RoPE
    gemm_qkv<<<dim3(24, BS_ROWS / 128), 256, G_SMEM>>>(x, Wq, Wk, Wv, pos,
                                                       Q, K, V);

    flash_mma<<<dim3(SS / 64, HH, BB), 128, F_SMEM>>>(Q, K, V, Aw);

    gemm_tf32<<<dim3(DD / 128, BS_ROWS / 128), 256, G_SMEM>>>(Aw, Wo, out);
}

// round 14
// speedup vs baseline: 1.1723x; 1.0180x over previous
#include <cuda_runtime.h>
#include <math_constants.h>
#include <cstdint>

#define BB 4
#define SS 2048
#define DD 1024
#define HH 16
#define DKK 64
#define BS_ROWS (BB*SS)   // 8192

// Persistent scratch (allocation-free rule: __device__ globals)
__device__ float g_Q[(size_t)BS_ROWS * DD];
__device__ float g_K[(size_t)BS_ROWS * DD];
__device__ float g_V[(size_t)BS_ROWS * DD];
__device__ float g_A[(size_t)BS_ROWS * DD];

__device__ __forceinline__ uint32_t f2tf32(float x) {
    uint32_t u;
    asm("cvt.rna.tf32.f32 %0, %1;" : "=r"(u) : "f"(x));
    return u;
}

__device__ __forceinline__ float ex2f(float x) {
    float y;
    asm("ex2.approx.f32 %0, %1;" : "=f"(y) : "f"(x));
    return y;
}

__device__ __forceinline__ uint32_t smem_u32(const void* p) {
    uint32_t a;
    asm("{ .reg .u64 t; cvta.to.shared.u64 t, %1; cvt.u32.u64 %0, t; }"
        : "=r"(a) : "l"(p));
    return a;
}

__device__ __forceinline__ void ldsm_x4(uint32_t& r0, uint32_t& r1,
                                        uint32_t& r2, uint32_t& r3,
                                        uint32_t addr) {
    asm volatile("ldmatrix.sync.aligned.m8n8.x4.shared.b16 {%0,%1,%2,%3}, [%4];"
                 : "=r"(r0), "=r"(r1), "=r"(r2), "=r"(r3) : "r"(addr));
}

__device__ __forceinline__ void mma_tf32(float& c0, float& c1, float& c2, float& c3,
                                         uint32_t a0, uint32_t a1, uint32_t a2, uint32_t a3,
                                         uint32_t b0, uint32_t b1) {
    asm volatile(
        "mma.sync.aligned.m16n8k8.row.col.f32.tf32.tf32.f32 "
        "{%0,%1,%2,%3}, {%4,%5,%6,%7}, {%8,%9}, {%0,%1,%2,%3};"
        : "+f"(c0), "+f"(c1), "+f"(c2), "+f"(c3)
        : "r"(a0), "r"(a1), "r"(a2), "r"(a3), "r"(b0), "r"(b1));
}

// ===========================================================================
// GEMM mainloop (tf32 mma.sync): 128 threads, 4 warps (2m x 2n),
// warp tile 64x64 (acc[4][8][4]). Block tile 128x128, BK=32.
// Double-buffered tf32 smem, one barrier per K-tile, ldmatrix.x4,
// register staging split in half (A then B) to cap live staging regs.
// ===========================================================================
#define BKG 32
#define GPAD 36
#define GSTAGE (128 * GPAD)               // words per stage per operand
#define G_SMEM (4 * GSTAGE * 4)           // 2 stages x (A+B) = 73728 B

__device__ __forceinline__ void gemm_mainloop(
    const float* __restrict__ Ag, const float* __restrict__ Bg,
    uint32_t* As, uint32_t* Bs,
    int t, int warp_m, int warp_n, float acc[4][8][4])
{
    const int lane = t & 31;
    const int lr0 = t >> 3;          // 0..15
    const int lc4 = (t & 7) << 2;    // 0,4,..,28

    const uint32_t STB = GSTAGE * 4;
    const uint32_t AOFF = 16 * GPAD * 4;   // 16-row byte stride

    const int arow = lane & 15;
    const int acol = (lane < 16) ? 0 : 4;
    const uint32_t aBase0 =
        smem_u32(&As[(size_t)(warp_m * 64 + arow) * GPAD + acol]);

    const int brow = ((lane >> 4) << 3) + (lane & 7);
    const int bcol = (lane & 8) ? 4 : 0;
    uint32_t bBase[4];
#pragma unroll
    for (int p = 0; p < 4; ++p)
        bBase[p] = smem_u32(&Bs[(size_t)(warp_n * 64 + p * 16 + brow) * GPAD + bcol]);

    const int NIT = DD / BKG;   // 32

    // Prologue: load + convert + store tile 0 into stage 0
    {
        float4 st[8];
#pragma unroll
        for (int p = 0; p < 8; ++p) {
            int r = p * 16 + lr0;
            st[p] = *(const float4*)(Ag + (size_t)r * DD + lc4);
        }
#pragma unroll
        for (int p = 0; p < 8; ++p) {
            int r = p * 16 + lr0;
            uint32_t* d = &As[(size_t)r * GPAD + lc4];
            d[0] = f2tf32(st[p].x); d[1] = f2tf32(st[p].y);
            d[2] = f2tf32(st[p].z); d[3] = f2tf32(st[p].w);
        }
#pragma unroll
        for (int p = 0; p < 8; ++p) {
            int r = p * 16 + lr0;
            st[p] = *(const float4*)(Bg + (size_t)r * DD + lc4);
        }
#pragma unroll
        for (int p = 0; p < 8; ++p) {
            int r = p * 16 + lr0;
            uint32_t* d = &Bs[(size_t)r * GPAD + lc4];
            d[0] = f2tf32(st[p].x); d[1] = f2tf32(st[p].y);
            d[2] = f2tf32(st[p].z); d[3] = f2tf32(st[p].w);
        }
    }
    __syncthreads();

    for (int kt = 0; kt < NIT; ++kt) {
        const uint32_t cur = (uint32_t)(kt & 1) * STB;
        const uint32_t nso = (uint32_t)((kt + 1) & 1) * GSTAGE;
        const int k1 = (kt + 1) * BKG;
        const bool more = (kt + 1 < NIT);

        float4 st[8];
        // Stage next A
        if (more) {
#pragma unroll
            for (int p = 0; p < 8; ++p) {
                int r = p * 16 + lr0;
                st[p] = *(const float4*)(Ag + (size_t)r * DD + k1 + lc4);
            }
        }

        // Compute kk = 0,1
#pragma unroll
        for (int kk = 0; kk < 2; ++kk) {
            const uint32_t ko = cur + kk * 32;
            uint32_t af[4][4];
#pragma unroll
            for (int mt = 0; mt < 4; ++mt)
                ldsm_x4(af[mt][0], af[mt][1], af[mt][2], af[mt][3],
                        aBase0 + mt * AOFF + ko);
#pragma unroll
            for (int p = 0; p < 4; ++p) {
                uint32_t b00, b01, b10, b11;
                ldsm_x4(b00, b01, b10, b11, bBase[p] + ko);
#pragma unroll
                for (int mt = 0; mt < 4; ++mt) {
                    mma_tf32(acc[mt][2*p][0], acc[mt][2*p][1],
                             acc[mt][2*p][2], acc[mt][2*p][3],
                             af[mt][0], af[mt][1], af[mt][2], af[mt][3], b00, b01);
                    mma_tf32(acc[mt][2*p+1][0], acc[mt][2*p+1][1],
                             acc[mt][2*p+1][2], acc[mt][2*p+1][3],
                             af[mt][0], af[mt][1], af[mt][2], af[mt][3], b10, b11);
                }
            }
        }

        // Store next A into alternate stage; stage next B
        if (more) {
#pragma unroll
            for (int p = 0; p < 8; ++p) {
                int r = p * 16 + lr0;
                uint32_t* d = &As[nso + (size_t)r * GPAD + lc4];
                d[0] = f2tf32(st[p].x); d[1] = f2tf32(st[p].y);
                d[2] = f2tf32(st[p].z); d[3] = f2tf32(st[p].w);
            }
#pragma unroll
            for (int p = 0; p < 8; ++p) {
                int r = p * 16 + lr0;
                st[p] = *(const float4*)(Bg + (size_t)r * DD + k1 + lc4);
            }
        }

        // Compute kk = 2,3
#pragma unroll
        for (int kk = 2; kk < 4; ++kk) {
            const uint32_t ko = cur + kk * 32;
            uint32_t af[4][4];
#pragma unroll
            for (int mt = 0; mt < 4; ++mt)
                ldsm_x4(af[mt][0], af[mt][1], af[mt][2], af[mt][3],
                        aBase0 + mt * AOFF + ko);
#pragma unroll
            for (int p = 0; p < 4; ++p) {
                uint32_t b00, b01, b10, b11;
                ldsm_x4(b00, b01, b10, b11, bBase[p] + ko);
#pragma unroll
                for (int mt = 0; mt < 4; ++mt) {
                    mma_tf32(acc[mt][2*p][0], acc[mt][2*p][1],
                             acc[mt][2*p][2], acc[mt][2*p][3],
                             af[mt][0], af[mt][1], af[mt][2], af[mt][3], b00, b01);
                    mma_tf32(acc[mt][2*p+1][0], acc[mt][2*p+1][1],
                             acc[mt][2*p+1][2], acc[mt][2*p+1][3],
                             af[mt][0], af[mt][1], af[mt][2], af[mt][3], b10, b11);
                }
            }
        }

        // Store next B into alternate stage
        if (more) {
#pragma unroll
            for (int p = 0; p < 8; ++p) {
                int r = p * 16 + lr0;
                uint32_t* d = &Bs[nso + (size_t)r * GPAD + lc4];
                d[0] = f2tf32(st[p].x); d[1] = f2tf32(st[p].y);
                d[2] = f2tf32(st[p].z); d[3] = f2tf32(st[p].w);
            }
        }
        __syncthreads();
    }
}

// ---------------------------------------------------------------------------
// Plain GEMM-NT (output projection).
// ---------------------------------------------------------------------------
__global__ __launch_bounds__(128, 2)
void gemm_tf32(const float* __restrict__ A, const float* __restrict__ Bw,
               float* __restrict__ C)
{
    extern __shared__ uint32_t gsm[];
    uint32_t* As = gsm;
    uint32_t* Bs = gsm + 2 * GSTAGE;

    const int t    = threadIdx.x;
    const int wid  = t >> 5;
    const int lane = t & 31;
    const int g    = lane >> 2;
    const int tg   = lane & 3;
    const int warp_m = wid & 1;
    const int warp_n = wid >> 1;

    const int rowBase = blockIdx.y * 128;
    const int colBase = blockIdx.x * 128;

    float acc[4][8][4];
#pragma unroll
    for (int mt = 0; mt < 4; ++mt)
#pragma unroll
        for (int nt = 0; nt < 8; ++nt)
#pragma unroll
            for (int i = 0; i < 4; ++i) acc[mt][nt][i] = 0.f;

    gemm_mainloop(A + (size_t)rowBase * DD, Bw + (size_t)colBase * DD,
                  As, Bs, t, warp_m, warp_n, acc);

#pragma unroll
    for (int mt = 0; mt < 4; ++mt) {
        const int r0 = rowBase + warp_m * 64 + mt * 16 + g;
#pragma unroll
        for (int nt = 0; nt < 8; ++nt) {
            const int c = colBase + warp_n * 64 + nt * 8 + tg * 2;
            *(float2*)(C + (size_t)r0 * DD + c) =
                make_float2(acc[mt][nt][0], acc[mt][nt][1]);
            *(float2*)(C + (size_t)(r0 + 8) * DD + c) =
                make_float2(acc[mt][nt][2], acc[mt][nt][3]);
        }
    }
}

// ---------------------------------------------------------------------------
// Fused QKV GEMM with RoPE epilogue on Q and K.
// grid (24, 64): blockIdx.x>>3 selects {Wq->Q, Wk->K, Wv->V}.
// ---------------------------------------------------------------------------
__global__ __launch_bounds__(128, 2)
void gemm_qkv(const float* __restrict__ x,
              const float* __restrict__ Wq, const float* __restrict__ Wk,
              const float* __restrict__ Wv, const int* __restrict__ pos,
              float* __restrict__ Q, float* __restrict__ K,
              float* __restrict__ V)
{
    extern __shared__ uint32_t gsm[];
    uint32_t* As = gsm;
    uint32_t* Bs = gsm + 2 * GSTAGE;

    const int t    = threadIdx.x;
    const int wid  = t >> 5;
    const int lane = t & 31;
    const int g    = lane >> 2;
    const int tg   = lane & 3;
    const int warp_m = wid & 1;
    const int warp_n = wid >> 1;

    const int sel = blockIdx.x >> 3;
    const float* Bw = (sel == 0) ? Wq : (sel == 1) ? Wk : Wv;
    float*       C  = (sel == 0) ? Q  : (sel == 1) ? K  : V;

    const int rowBase = blockIdx.y * 128;
    const int colBase = (blockIdx.x & 7) * 128;

    float acc[4][8][4];
#pragma unroll
    for (int mt = 0; mt < 4; ++mt)
#pragma unroll
        for (int nt = 0; nt < 8; ++nt)
#pragma unroll
            for (int i = 0; i < 4; ++i) acc[mt][nt][i] = 0.f;

    gemm_mainloop(x + (size_t)rowBase * DD, Bw + (size_t)colBase * DD,
                  As, Bs, t, warp_m, warp_n, acc);

    if (sel < 2) {
        // RoPE epilogue (Q, K): store pair (c, c+1) is the rope pair.
#pragma unroll
        for (int mt = 0; mt < 4; ++mt) {
            const int r0 = rowBase + warp_m * 64 + mt * 16 + g;
            const float p0 = (float)pos[r0 & (SS - 1)];
            const float p1 = (float)pos[(r0 + 8) & (SS - 1)];
#pragma unroll
            for (int nt = 0; nt < 8; ++nt) {
                const int c = colBase + warp_n * 64 + nt * 8 + tg * 2;
                const int j = (c & 63) >> 1;
                const float inv = expf(-(float)j * 0.28782313662425572f);
                float sn0, cs0, sn1, cs1;
                sincosf(p0 * inv, &sn0, &cs0);
                sincosf(p1 * inv, &sn1, &cs1);
                float x1 = acc[mt][nt][0], x2 = acc[mt][nt][1];
                *(float2*)(C + (size_t)r0 * DD + c) =
                    make_float2(x1 * cs0 - x2 * sn0, x1 * sn0 + x2 * cs0);
                x1 = acc[mt][nt][2]; x2 = acc[mt][nt][3];
                *(float2*)(C + (size_t)(r0 + 8) * DD + c) =
                    make_float2(x1 * cs1 - x2 * sn1, x1 * sn1 + x2 * cs1);
            }
        }
    } else {
#pragma unroll
        for (int mt = 0; mt < 4; ++mt) {
            const int r0 = rowBase + warp_m * 64 + mt * 16 + g;
#pragma unroll
            for (int nt = 0; nt < 8; ++nt) {
                const int c = colBase + warp_n * 64 + nt * 8 + tg * 2;
                *(float2*)(C + (size_t)r0 * DD + c) =
                    make_float2(acc[mt][nt][0], acc[mt][nt][1]);
                *(float2*)(C + (size_t)(r0 + 8) * DD + c) =
                    make_float2(acc[mt][nt][2], acc[mt][nt][3]);
            }
        }
    }
}

// ===========================================================================
// Tensor-core flash attention (causal), 3x-tf32 error-compensated.
// Br=Bc=64, 128 threads (4 warps), warp owns 16 query rows.
// ===========================================================================
#define FP 68
#define F_SMEM (6 * 64 * FP * 4)   // 104448 B

__global__ __launch_bounds__(128, 2)
void flash_mma(const float* __restrict__ Q, const float* __restrict__ K,
               const float* __restrict__ V, float* __restrict__ O)
{
    extern __shared__ uint32_t fsm[];
    uint32_t* KsH = fsm;
    uint32_t* KsL = KsH + 64 * FP;
    uint32_t* VsH = KsL + 64 * FP;
    uint32_t* VsL = VsH + 64 * FP;
    uint32_t* PsH = VsL + 64 * FP;
    uint32_t* PsL = PsH + 64 * FP;

    const int t    = threadIdx.x;
    const int wid  = t >> 5;
    const int lane = t & 31;
    const int g    = lane >> 2;
    const int tg   = lane & 3;
    const int qbase = blockIdx.x * 64;

    const size_t hb = (size_t)blockIdx.z * SS * DD + (size_t)blockIdx.y * DKK;
    const float* Qg = Q + hb;
    const float* Kg = K + hb;
    const float* Vg = V + hb;
    float*       Og = O + hb;

    const float QS = 0.125f * 1.4426950408889634f;   // 1/sqrt(64) * log2(e)

#pragma unroll
    for (int p = 0; p < 8; ++p) {
        int idx = p * 128 + t;
        int r = idx >> 4, c = (idx & 15) << 2;
        float4 v = *(const float4*)(Qg + (size_t)(qbase + r) * DD + c);
        float f0 = v.x * QS, f1 = v.y * QS, f2 = v.z * QS, f3 = v.w * QS;
        uint4 h, l;
        h.x = f2tf32(f0); l.x = f2tf32(f0 - __uint_as_float(h.x));
        h.y = f2tf32(f1); l.y = f2tf32(f1 - __uint_as_float(h.y));
        h.z = f2tf32(f2); l.z = f2tf32(f2 - __uint_as_float(h.z));
        h.w = f2tf32(f3); l.w = f2tf32(f3 - __uint_as_float(h.w));
        *(uint4*)&KsH[r * FP + c] = h;
        *(uint4*)&KsL[r * FP + c] = l;
    }
    __syncthreads();

    uint32_t qh[8][4], ql[8][4];
    const int arow = wid * 16 + g;
#pragma unroll
    for (int ks = 0; ks < 8; ++ks) {
        int kc = ks * 8 + tg;
        qh[ks][0] = KsH[arow * FP + kc];
        qh[ks][1] = KsH[(arow + 8) * FP + kc];
        qh[ks][2] = KsH[arow * FP + kc + 4];
        qh[ks][3] = KsH[(arow + 8) * FP + kc + 4];
        ql[ks][0] = KsL[arow * FP + kc];
        ql[ks][1] = KsL[(arow + 8) * FP + kc];
        ql[ks][2] = KsL[arow * FP + kc + 4];
        ql[ks][3] = KsL[(arow + 8) * FP + kc + 4];
    }
    __syncthreads();

    float m0 = -CUDART_INF_F, m1 = -CUDART_INF_F, l0 = 0.f, l1 = 0.f;
    float o[8][4];
#pragma unroll
    for (int nt = 0; nt < 8; ++nt)
#pragma unroll
        for (int i = 0; i < 4; ++i) o[nt][i] = 0.f;

    for (int kt = 0; kt <= (int)blockIdx.x; ++kt) {
        const int kb = kt * 64;

#pragma unroll
        for (int p = 0; p < 8; ++p) {
            int idx = p * 128 + t;
            int r = idx >> 4, c = (idx & 15) << 2;
            float4 kv = *(const float4*)(Kg + (size_t)(kb + r) * DD + c);
            float4 vv = *(const float4*)(Vg + (size_t)(kb + r) * DD + c);
            uint4 kh, kl, vh, vl;
            kh.x = f2tf32(kv.x); kl.x = f2tf32(kv.x - __uint_as_float(kh.x));
            kh.y = f2tf32(kv.y); kl.y = f2tf32(kv.y - __uint_as_float(kh.y));
            kh.z = f2tf32(kv.z); kl.z = f2tf32(kv.z - __uint_as_float(kh.z));
            kh.w = f2tf32(kv.w); kl.w = f2tf32(kv.w - __uint_as_float(kh.w));
            vh.x = f2tf32(vv.x); vl.x = f2tf32(vv.x - __uint_as_float(vh.x));
            vh.y = f2tf32(vv.y); vl.y = f2tf32(vv.y - __uint_as_float(vh.y));
            vh.z = f2tf32(vv.z); vl.z = f2tf32(vv.z - __uint_as_float(vh.z));
            vh.w = f2tf32(vv.w); vl.w = f2tf32(vv.w - __uint_as_float(vh.w));
            *(uint4*)&KsH[r * FP + c] = kh;
            *(uint4*)&KsL[r * FP + c] = kl;
            *(uint4*)&VsH[r * FP + c] = vh;
            *(uint4*)&VsL[r * FP + c] = vl;
        }
        __syncthreads();

        float s[8][4];
#pragma unroll
        for (int nt = 0; nt < 8; ++nt)
#pragma unroll
            for (int i = 0; i < 4; ++i) s[nt][i] = 0.f;

#pragma unroll
        for (int ks = 0; ks < 8; ++ks) {
            const int kc = ks * 8;
#pragma unroll
            for (int nt = 0; nt < 8; ++nt) {
                const int br = (nt * 8 + g) * FP + kc;
                uint32_t bh0 = KsH[br + tg], bh1 = KsH[br + tg + 4];
                uint32_t bl0 = KsL[br + tg], bl1 = KsL[br + tg + 4];
                mma_tf32(s[nt][0], s[nt][1], s[nt][2], s[nt][3],
                         qh[ks][0], qh[ks][1], qh[ks][2], qh[ks][3], bh0, bh1);
                mma_tf32(s[nt][0], s[nt][1], s[nt][2], s[nt][3],
                         ql[ks][0], ql[ks][1], ql[ks][2], ql[ks][3], bh0, bh1);
                mma_tf32(s[nt][0], s[nt][1], s[nt][2], s[nt][3],
                         qh[ks][0], qh[ks][1], qh[ks][2], qh[ks][3], bl0, bl1);
            }
        }

        if (kt == (int)blockIdx.x) {
            const int row0 = qbase + wid * 16 + g;
#pragma unroll
            for (int nt = 0; nt < 8; ++nt) {
                const int c0 = kb + nt * 8 + 2 * tg;
                if (c0     > row0)     s[nt][0] = -CUDART_INF_F;
                if (c0 + 1 > row0)     s[nt][1] = -CUDART_INF_F;
                if (c0     > row0 + 8) s[nt][2] = -CUDART_INF_F;
                if (c0 + 1 > row0 + 8) s[nt][3] = -CUDART_INF_F;
            }
        }

        float mx0 = -CUDART_INF_F, mx1 = -CUDART_INF_F;
#pragma unroll
        for (int nt = 0; nt < 8; ++nt) {
            mx0 = fmaxf(mx0, fmaxf(s[nt][0], s[nt][1]));
            mx1 = fmaxf(mx1, fmaxf(s[nt][2], s[nt][3]));
        }
        mx0 = fmaxf(mx0, __shfl_xor_sync(0xffffffffu, mx0, 1));
        mx0 = fmaxf(mx0, __shfl_xor_sync(0xffffffffu, mx0, 2));
        mx1 = fmaxf(mx1, __shfl_xor_sync(0xffffffffu, mx1, 1));
        mx1 = fmaxf(mx1, __shfl_xor_sync(0xffffffffu, mx1, 2));

        float mn0 = fmaxf(m0, mx0), mn1 = fmaxf(m1, mx1);
        float cr0 = ex2f(m0 - mn0), cr1 = ex2f(m1 - mn1);
        float sum0 = 0.f, sum1 = 0.f;
        const int prow = (wid * 16 + g) * FP;
#pragma unroll
        for (int nt = 0; nt < 8; ++nt) {
            float p0 = ex2f(s[nt][0] - mn0), p1 = ex2f(s[nt][1] - mn0);
            float p2 = ex2f(s[nt][2] - mn1), p3 = ex2f(s[nt][3] - mn1);
            sum0 += p0 + p1;
            sum1 += p2 + p3;
            uint32_t h0 = f2tf32(p0), h1 = f2tf32(p1);
            uint32_t h2 = f2tf32(p2), h3 = f2tf32(p3);
            const int pc = nt * 8 + 2 * tg;
            *(uint2*)&PsH[prow + pc]          = make_uint2(h0, h1);
            *(uint2*)&PsH[prow + 8 * FP + pc] = make_uint2(h2, h3);
            *(uint2*)&PsL[prow + pc]          = make_uint2(
                f2tf32(p0 - __uint_as_float(h0)), f2tf32(p1 - __uint_as_float(h1)));
            *(uint2*)&PsL[prow + 8 * FP + pc] = make_uint2(
                f2tf32(p2 - __uint_as_float(h2)), f2tf32(p3 - __uint_as_float(h3)));
        }
        sum0 += __shfl_xor_sync(0xffffffffu, sum0, 1);
        sum0 += __shfl_xor_sync(0xffffffffu, sum0, 2);
        sum1 += __shfl_xor_sync(0xffffffffu, sum1, 1);
        sum1 += __shfl_xor_sync(0xffffffffu, sum1, 2);
        l0 = l0 * cr0 + sum0;
        l1 = l1 * cr1 + sum1;
        m0 = mn0; m1 = mn1;
#pragma unroll
        for (int nt = 0; nt < 8; ++nt) {
            o[nt][0] *= cr0; o[nt][1] *= cr0;
            o[nt][2] *= cr1; o[nt][3] *= cr1;
        }
        __syncwarp();

#pragma unroll
        for (int ks = 0; ks < 8; ++ks) {
            const int kc = ks * 8;
            uint32_t ah0 = PsH[prow + kc + tg];
            uint32_t ah1 = PsH[prow + 8 * FP + kc + tg];
            uint32_t ah2 = PsH[prow + kc + tg + 4];
            uint32_t ah3 = PsH[prow + 8 * FP + kc + tg + 4];
            uint32_t al0 = PsL[prow + kc + tg];
            uint32_t al1 = PsL[prow + 8 * FP + kc + tg];
            uint32_t al2 = PsL[prow + kc + tg + 4];
            uint32_t al3 = PsL[prow + 8 * FP + kc + tg + 4];
#pragma unroll
            for (int nt = 0; nt < 8; ++nt) {
                const int vb = (kc + tg) * FP + nt * 8 + g;
                uint32_t bh0 = VsH[vb], bh1 = VsH[vb + 4 * FP];
                uint32_t bl0 = VsL[vb], bl1 = VsL[vb + 4 * FP];
                mma_tf32(o[nt][0], o[nt][1], o[nt][2], o[nt][3],
                         ah0, ah1, ah2, ah3, bh0, bh1);
                mma_tf32(o[nt][0], o[nt][1], o[nt][2], o[nt][3],
                         al0, al1, al2, al3, bh0, bh1);
                mma_tf32(o[nt][0], o[nt][1], o[nt][2], o[nt][3],
                         ah0, ah1, ah2, ah3, bl0, bl1);
            }
        }
        __syncthreads();
    }

    const float i0 = 1.0f / l0, i1 = 1.0f / l1;
    const int row0 = qbase + wid * 16 + g;
#pragma unroll
    for (int nt = 0; nt < 8; ++nt) {
        const int c = nt * 8 + 2 * tg;
        *(float2*)(Og + (size_t)row0 * DD + c) =
            make_float2(o[nt][0] * i0, o[nt][1] * i0);
        *(float2*)(Og + (size_t)(row0 + 8) * DD + c) =
            make_float2(o[nt][2] * i1, o[nt][3] * i1);
    }
}

// ---------------------------------------------------------------------------
extern "C" void kernel_launch(void* const* d_in, const int* in_sizes, int n_in,
                              void* d_out, int out_size)
{
    const float* x   = (const float*)d_in[0];
    const int*   pos = (const int*)  d_in[1];
    const float* Wq  = (const float*)d_in[2];
    const float* Wk  = (const float*)d_in[3];
    const float* Wv  = (const float*)d_in[4];
    const float* Wo  = (const float*)d_in[5];
    float* out = (float*)d_out;

    float *Q, *K, *V, *Aw;
    cudaGetSymbolAddress((void**)&Q,  g_Q);
    cudaGetSymbolAddress((void**)&K,  g_K);
    cudaGetSymbolAddress((void**)&V,  g_V);
    cudaGetSymbolAddress((void**)&Aw, g_A);

    cudaFuncSetAttribute(gemm_tf32, cudaFuncAttributeMaxDynamicSharedMemorySize,
                         G_SMEM);
    cudaFuncSetAttribute(gemm_qkv, cudaFuncAttributeMaxDynamicSharedMemorySize,
                         G_SMEM);
    cudaFuncSetAttribute(flash_mma, cudaFuncAttributeMaxDynamicSharedMemorySize,
                         F_SMEM);

    // Fused QKV projection + RoPE
    gemm_qkv<<<dim3(24, BS_ROWS / 128), 128, G_SMEM>>>(x, Wq, Wk, Wv, pos,
                                                       Q, K, V);

    flash_mma<<<dim3(SS / 64, HH, BB), 128, F_SMEM>>>(Q, K, V, Aw);

    gemm_tf32<<<dim3(DD / 128, BS_ROWS / 128), 128, G_SMEM>>>(Aw, Wo, out);
}

// round 15
// speedup vs baseline: 1.3103x; 1.1177x over previous
#include <cuda_runtime.h>
#include <cuda_bf16.h>
#include <math_constants.h>
#include <cstdint>

#define BB 4
#define SS 2048
#define DD 1024
#define HH 16
#define DKK 64
#define BS_ROWS (BB*SS)   // 8192

// Persistent scratch (allocation-free rule: __device__ globals)
__device__ float g_Q[(size_t)BS_ROWS * DD];
__device__ float g_K[(size_t)BS_ROWS * DD];
__device__ float g_V[(size_t)BS_ROWS * DD];
__device__ float g_A[(size_t)BS_ROWS * DD];

__device__ __forceinline__ uint32_t f2tf32(float x) {
    uint32_t u;
    asm("cvt.rna.tf32.f32 %0, %1;" : "=r"(u) : "f"(x));
    return u;
}

__device__ __forceinline__ float ex2f(float x) {
    float y;
    asm("ex2.approx.f32 %0, %1;" : "=f"(y) : "f"(x));
    return y;
}

// pack two floats as bf16x2: lo -> low 16 bits, hi -> high 16 bits
__device__ __forceinline__ uint32_t pack_bf16(float lo, float hi) {
    uint32_t u;
    asm("cvt.rn.bf16x2.f32 %0, %1, %2;" : "=r"(u) : "f"(hi), "f"(lo));
    return u;
}

__device__ __forceinline__ uint32_t smem_u32(const void* p) {
    uint32_t a;
    asm("{ .reg .u64 t; cvta.to.shared.u64 t, %1; cvt.u32.u64 %0, t; }"
        : "=r"(a) : "l"(p));
    return a;
}

__device__ __forceinline__ void ldsm_x4(uint32_t& r0, uint32_t& r1,
                                        uint32_t& r2, uint32_t& r3,
                                        uint32_t addr) {
    asm volatile("ldmatrix.sync.aligned.m8n8.x4.shared.b16 {%0,%1,%2,%3}, [%4];"
                 : "=r"(r0), "=r"(r1), "=r"(r2), "=r"(r3) : "r"(addr));
}

__device__ __forceinline__ void mma_tf32(float& c0, float& c1, float& c2, float& c3,
                                         uint32_t a0, uint32_t a1, uint32_t a2, uint32_t a3,
                                         uint32_t b0, uint32_t b1) {
    asm volatile(
        "mma.sync.aligned.m16n8k8.row.col.f32.tf32.tf32.f32 "
        "{%0,%1,%2,%3}, {%4,%5,%6,%7}, {%8,%9}, {%0,%1,%2,%3};"
        : "+f"(c0), "+f"(c1), "+f"(c2), "+f"(c3)
        : "r"(a0), "r"(a1), "r"(a2), "r"(a3), "r"(b0), "r"(b1));
}

__device__ __forceinline__ void mma_bf16(float& c0, float& c1, float& c2, float& c3,
                                         uint32_t a0, uint32_t a1, uint32_t a2, uint32_t a3,
                                         uint32_t b0, uint32_t b1) {
    asm volatile(
        "mma.sync.aligned.m16n8k16.row.col.f32.bf16.bf16.f32 "
        "{%0,%1,%2,%3}, {%4,%5,%6,%7}, {%8,%9}, {%0,%1,%2,%3};"
        : "+f"(c0), "+f"(c1), "+f"(c2), "+f"(c3)
        : "r"(a0), "r"(a1), "r"(a2), "r"(a3), "r"(b0), "r"(b1));
}

// ===========================================================================
// GEMM mainloop (tf32 mma.sync): 128 threads, 4 warps (2m x 2n),
// warp tile 64x64 (acc[4][8][4]). Block tile 128x128, BK=32.  (R14 version)
// ===========================================================================
#define BKG 32
#define GPAD 36
#define GSTAGE (128 * GPAD)               // words per stage per operand
#define G_SMEM (4 * GSTAGE * 4)           // 2 stages x (A+B) = 73728 B

__device__ __forceinline__ void gemm_mainloop(
    const float* __restrict__ Ag, const float* __restrict__ Bg,
    uint32_t* As, uint32_t* Bs,
    int t, int warp_m, int warp_n, float acc[4][8][4])
{
    const int lane = t & 31;
    const int lr0 = t >> 3;          // 0..15
    const int lc4 = (t & 7) << 2;    // 0,4,..,28

    const uint32_t STB = GSTAGE * 4;
    const uint32_t AOFF = 16 * GPAD * 4;

    const int arow = lane & 15;
    const int acol = (lane < 16) ? 0 : 4;
    const uint32_t aBase0 =
        smem_u32(&As[(size_t)(warp_m * 64 + arow) * GPAD + acol]);

    const int brow = ((lane >> 4) << 3) + (lane & 7);
    const int bcol = (lane & 8) ? 4 : 0;
    uint32_t bBase[4];
#pragma unroll
    for (int p = 0; p < 4; ++p)
        bBase[p] = smem_u32(&Bs[(size_t)(warp_n * 64 + p * 16 + brow) * GPAD + bcol]);

    const int NIT = DD / BKG;   // 32

    {
        float4 st[8];
#pragma unroll
        for (int p = 0; p < 8; ++p) {
            int r = p * 16 + lr0;
            st[p] = *(const float4*)(Ag + (size_t)r * DD + lc4);
        }
#pragma unroll
        for (int p = 0; p < 8; ++p) {
            int r = p * 16 + lr0;
            uint32_t* d = &As[(size_t)r * GPAD + lc4];
            d[0] = f2tf32(st[p].x); d[1] = f2tf32(st[p].y);
            d[2] = f2tf32(st[p].z); d[3] = f2tf32(st[p].w);
        }
#pragma unroll
        for (int p = 0; p < 8; ++p) {
            int r = p * 16 + lr0;
            st[p] = *(const float4*)(Bg + (size_t)r * DD + lc4);
        }
#pragma unroll
        for (int p = 0; p < 8; ++p) {
            int r = p * 16 + lr0;
            uint32_t* d = &Bs[(size_t)r * GPAD + lc4];
            d[0] = f2tf32(st[p].x); d[1] = f2tf32(st[p].y);
            d[2] = f2tf32(st[p].z); d[3] = f2tf32(st[p].w);
        }
    }
    __syncthreads();

    for (int kt = 0; kt < NIT; ++kt) {
        const uint32_t cur = (uint32_t)(kt & 1) * STB;
        const uint32_t nso = (uint32_t)((kt + 1) & 1) * GSTAGE;
        const int k1 = (kt + 1) * BKG;
        const bool more = (kt + 1 < NIT);

        float4 st[8];
        if (more) {
#pragma unroll
            for (int p = 0; p < 8; ++p) {
                int r = p * 16 + lr0;
                st[p] = *(const float4*)(Ag + (size_t)r * DD + k1 + lc4);
            }
        }

#pragma unroll
        for (int kk = 0; kk < 2; ++kk) {
            const uint32_t ko = cur + kk * 32;
            uint32_t af[4][4];
#pragma unroll
            for (int mt = 0; mt < 4; ++mt)
                ldsm_x4(af[mt][0], af[mt][1], af[mt][2], af[mt][3],
                        aBase0 + mt * AOFF + ko);
#pragma unroll
            for (int p = 0; p < 4; ++p) {
                uint32_t b00, b01, b10, b11;
                ldsm_x4(b00, b01, b10, b11, bBase[p] + ko);
#pragma unroll
                for (int mt = 0; mt < 4; ++mt) {
                    mma_tf32(acc[mt][2*p][0], acc[mt][2*p][1],
                             acc[mt][2*p][2], acc[mt][2*p][3],
                             af[mt][0], af[mt][1], af[mt][2], af[mt][3], b00, b01);
                    mma_tf32(acc[mt][2*p+1][0], acc[mt][2*p+1][1],
                             acc[mt][2*p+1][2], acc[mt][2*p+1][3],
                             af[mt][0], af[mt][1], af[mt][2], af[mt][3], b10, b11);
                }
            }
        }

        if (more) {
#pragma unroll
            for (int p = 0; p < 8; ++p) {
                int r = p * 16 + lr0;
                uint32_t* d = &As[nso + (size_t)r * GPAD + lc4];
                d[0] = f2tf32(st[p].x); d[1] = f2tf32(st[p].y);
                d[2] = f2tf32(st[p].z); d[3] = f2tf32(st[p].w);
            }
#pragma unroll
            for (int p = 0; p < 8; ++p) {
                int r = p * 16 + lr0;
                st[p] = *(const float4*)(Bg + (size_t)r * DD + k1 + lc4);
            }
        }

#pragma unroll
        for (int kk = 2; kk < 4; ++kk) {
            const uint32_t ko = cur + kk * 32;
            uint32_t af[4][4];
#pragma unroll
            for (int mt = 0; mt < 4; ++mt)
                ldsm_x4(af[mt][0], af[mt][1], af[mt][2], af[mt][3],
                        aBase0 + mt * AOFF + ko);
#pragma unroll
            for (int p = 0; p < 4; ++p) {
                uint32_t b00, b01, b10, b11;
                ldsm_x4(b00, b01, b10, b11, bBase[p] + ko);
#pragma unroll
                for (int mt = 0; mt < 4; ++mt) {
                    mma_tf32(acc[mt][2*p][0], acc[mt][2*p][1],
                             acc[mt][2*p][2], acc[mt][2*p][3],
                             af[mt][0], af[mt][1], af[mt][2], af[mt][3], b00, b01);
                    mma_tf32(acc[mt][2*p+1][0], acc[mt][2*p+1][1],
                             acc[mt][2*p+1][2], acc[mt][2*p+1][3],
                             af[mt][0], af[mt][1], af[mt][2], af[mt][3], b10, b11);
                }
            }
        }

        if (more) {
#pragma unroll
            for (int p = 0; p < 8; ++p) {
                int r = p * 16 + lr0;
                uint32_t* d = &Bs[nso + (size_t)r * GPAD + lc4];
                d[0] = f2tf32(st[p].x); d[1] = f2tf32(st[p].y);
                d[2] = f2tf32(st[p].z); d[3] = f2tf32(st[p].w);
            }
        }
        __syncthreads();
    }
}

// ---------------------------------------------------------------------------
// Plain GEMM-NT (output projection).
// ---------------------------------------------------------------------------
__global__ __launch_bounds__(128, 2)
void gemm_tf32(const float* __restrict__ A, const float* __restrict__ Bw,
               float* __restrict__ C)
{
    extern __shared__ uint32_t gsm[];
    uint32_t* As = gsm;
    uint32_t* Bs = gsm + 2 * GSTAGE;

    const int t    = threadIdx.x;
    const int wid  = t >> 5;
    const int lane = t & 31;
    const int g    = lane >> 2;
    const int tg   = lane & 3;
    const int warp_m = wid & 1;
    const int warp_n = wid >> 1;

    const int rowBase = blockIdx.y * 128;
    const int colBase = blockIdx.x * 128;

    float acc[4][8][4];
#pragma unroll
    for (int mt = 0; mt < 4; ++mt)
#pragma unroll
        for (int nt = 0; nt < 8; ++nt)
#pragma unroll
            for (int i = 0; i < 4; ++i) acc[mt][nt][i] = 0.f;

    gemm_mainloop(A + (size_t)rowBase * DD, Bw + (size_t)colBase * DD,
                  As, Bs, t, warp_m, warp_n, acc);

#pragma unroll
    for (int mt = 0; mt < 4; ++mt) {
        const int r0 = rowBase + warp_m * 64 + mt * 16 + g;
#pragma unroll
        for (int nt = 0; nt < 8; ++nt) {
            const int c = colBase + warp_n * 64 + nt * 8 + tg * 2;
            *(float2*)(C + (size_t)r0 * DD + c) =
                make_float2(acc[mt][nt][0], acc[mt][nt][1]);
            *(float2*)(C + (size_t)(r0 + 8) * DD + c) =
                make_float2(acc[mt][nt][2], acc[mt][nt][3]);
        }
    }
}

// ---------------------------------------------------------------------------
// Fused QKV GEMM with RoPE epilogue on Q and K.
// ---------------------------------------------------------------------------
__global__ __launch_bounds__(128, 2)
void gemm_qkv(const float* __restrict__ x,
              const float* __restrict__ Wq, const float* __restrict__ Wk,
              const float* __restrict__ Wv, const int* __restrict__ pos,
              float* __restrict__ Q, float* __restrict__ K,
              float* __restrict__ V)
{
    extern __shared__ uint32_t gsm[];
    uint32_t* As = gsm;
    uint32_t* Bs = gsm + 2 * GSTAGE;

    const int t    = threadIdx.x;
    const int wid  = t >> 5;
    const int lane = t & 31;
    const int g    = lane >> 2;
    const int tg   = lane & 3;
    const int warp_m = wid & 1;
    const int warp_n = wid >> 1;

    const int sel = blockIdx.x >> 3;
    const float* Bw = (sel == 0) ? Wq : (sel == 1) ? Wk : Wv;
    float*       C  = (sel == 0) ? Q  : (sel == 1) ? K  : V;

    const int rowBase = blockIdx.y * 128;
    const int colBase = (blockIdx.x & 7) * 128;

    float acc[4][8][4];
#pragma unroll
    for (int mt = 0; mt < 4; ++mt)
#pragma unroll
        for (int nt = 0; nt < 8; ++nt)
#pragma unroll
            for (int i = 0; i < 4; ++i) acc[mt][nt][i] = 0.f;

    gemm_mainloop(x + (size_t)rowBase * DD, Bw + (size_t)colBase * DD,
                  As, Bs, t, warp_m, warp_n, acc);

    if (sel < 2) {
#pragma unroll
        for (int mt = 0; mt < 4; ++mt) {
            const int r0 = rowBase + warp_m * 64 + mt * 16 + g;
            const float p0 = (float)pos[r0 & (SS - 1)];
            const float p1 = (float)pos[(r0 + 8) & (SS - 1)];
#pragma unroll
            for (int nt = 0; nt < 8; ++nt) {
                const int c = colBase + warp_n * 64 + nt * 8 + tg * 2;
                const int j = (c & 63) >> 1;
                const float inv = expf(-(float)j * 0.28782313662425572f);
                float sn0, cs0, sn1, cs1;
                sincosf(p0 * inv, &sn0, &cs0);
                sincosf(p1 * inv, &sn1, &cs1);
                float x1 = acc[mt][nt][0], x2 = acc[mt][nt][1];
                *(float2*)(C + (size_t)r0 * DD + c) =
                    make_float2(x1 * cs0 - x2 * sn0, x1 * sn0 + x2 * cs0);
                x1 = acc[mt][nt][2]; x2 = acc[mt][nt][3];
                *(float2*)(C + (size_t)(r0 + 8) * DD + c) =
                    make_float2(x1 * cs1 - x2 * sn1, x1 * sn1 + x2 * cs1);
            }
        }
    } else {
#pragma unroll
        for (int mt = 0; mt < 4; ++mt) {
            const int r0 = rowBase + warp_m * 64 + mt * 16 + g;
#pragma unroll
            for (int nt = 0; nt < 8; ++nt) {
                const int c = colBase + warp_n * 64 + nt * 8 + tg * 2;
                *(float2*)(C + (size_t)r0 * DD + c) =
                    make_float2(acc[mt][nt][0], acc[mt][nt][1]);
                *(float2*)(C + (size_t)(r0 + 8) * DD + c) =
                    make_float2(acc[mt][nt][2], acc[mt][nt][3]);
            }
        }
    }
}

// ===========================================================================
// Tensor-core flash attention (causal).
//   S = QK^T: 3x-bf16 error-compensated (m16n8k16, packed bf16x2 words)
//   PV:       3x-tf32 error-compensated (m16n8k8)
// Br=Bc=64, 128 threads (4 warps), warp owns 16 query rows.
// ===========================================================================
#define FP 68      // tf32 row stride (V, P)
#define PKW 36     // packed-bf16 row stride (Q, K): 32 words + pad
#define F_SMEM ((2 * 64 * PKW + 4 * 64 * FP) * 4)   // 88064 B

__global__ __launch_bounds__(128, 2)
void flash_mma(const float* __restrict__ Q, const float* __restrict__ K,
               const float* __restrict__ V, float* __restrict__ O)
{
    extern __shared__ uint32_t fsm[];
    uint32_t* KsHb = fsm;                  // 64 x PKW packed bf16 (K hi)
    uint32_t* KsLb = KsHb + 64 * PKW;      // (K lo)
    uint32_t* VsH  = KsLb + 64 * PKW;      // 64 x FP tf32 (V hi)
    uint32_t* VsL  = VsH + 64 * FP;
    uint32_t* PsH  = VsL + 64 * FP;
    uint32_t* PsL  = PsH + 64 * FP;

    const int t    = threadIdx.x;
    const int wid  = t >> 5;
    const int lane = t & 31;
    const int g    = lane >> 2;
    const int tg   = lane & 3;
    const int qbase = blockIdx.x * 64;

    const size_t hb = (size_t)blockIdx.z * SS * DD + (size_t)blockIdx.y * DKK;
    const float* Qg = Q + hb;
    const float* Kg = K + hb;
    const float* Vg = V + hb;
    float*       Og = O + hb;

    const float QS = 0.125f * 1.4426950408889634f;   // 1/sqrt(64) * log2(e)

    // Stage Q (scaled) hi/lo packed bf16 into KsHb/KsLb, then to registers
#pragma unroll
    for (int p = 0; p < 8; ++p) {
        int idx = p * 128 + t;
        int r = idx >> 4, c = (idx & 15) << 2;
        float4 v = *(const float4*)(Qg + (size_t)(qbase + r) * DD + c);
        float f0 = v.x * QS, f1 = v.y * QS, f2 = v.z * QS, f3 = v.w * QS;
        float h0 = __bfloat162float(__float2bfloat16(f0));
        float h1 = __bfloat162float(__float2bfloat16(f1));
        float h2 = __bfloat162float(__float2bfloat16(f2));
        float h3 = __bfloat162float(__float2bfloat16(f3));
        *(uint2*)&KsHb[r * PKW + (c >> 1)] =
            make_uint2(pack_bf16(h0, h1), pack_bf16(h2, h3));
        *(uint2*)&KsLb[r * PKW + (c >> 1)] =
            make_uint2(pack_bf16(f0 - h0, f1 - h1), pack_bf16(f2 - h2, f3 - h3));
    }
    __syncthreads();

    uint32_t qh[4][4], ql[4][4];
    const int arow = wid * 16 + g;
#pragma unroll
    for (int ks = 0; ks < 4; ++ks) {
        int kc = ks * 8 + tg;
        qh[ks][0] = KsHb[arow * PKW + kc];
        qh[ks][1] = KsHb[(arow + 8) * PKW + kc];
        qh[ks][2] = KsHb[arow * PKW + kc + 4];
        qh[ks][3] = KsHb[(arow + 8) * PKW + kc + 4];
        ql[ks][0] = KsLb[arow * PKW + kc];
        ql[ks][1] = KsLb[(arow + 8) * PKW + kc];
        ql[ks][2] = KsLb[arow * PKW + kc + 4];
        ql[ks][3] = KsLb[(arow + 8) * PKW + kc + 4];
    }
    __syncthreads();

    float m0 = -CUDART_INF_F, m1 = -CUDART_INF_F, l0 = 0.f, l1 = 0.f;
    float o[8][4];
#pragma unroll
    for (int nt = 0; nt < 8; ++nt)
#pragma unroll
        for (int i = 0; i < 4; ++i) o[nt][i] = 0.f;

    for (int kt = 0; kt <= (int)blockIdx.x; ++kt) {
        const int kb = kt * 64;

        // Load K (packed bf16 hi/lo) and V (tf32 hi/lo)
#pragma unroll
        for (int p = 0; p < 8; ++p) {
            int idx = p * 128 + t;
            int r = idx >> 4, c = (idx & 15) << 2;
            float4 kv = *(const float4*)(Kg + (size_t)(kb + r) * DD + c);
            float4 vv = *(const float4*)(Vg + (size_t)(kb + r) * DD + c);
            float h0 = __bfloat162float(__float2bfloat16(kv.x));
            float h1 = __bfloat162float(__float2bfloat16(kv.y));
            float h2 = __bfloat162float(__float2bfloat16(kv.z));
            float h3 = __bfloat162float(__float2bfloat16(kv.w));
            *(uint2*)&KsHb[r * PKW + (c >> 1)] =
                make_uint2(pack_bf16(h0, h1), pack_bf16(h2, h3));
            *(uint2*)&KsLb[r * PKW + (c >> 1)] = make_uint2(
                pack_bf16(kv.x - h0, kv.y - h1), pack_bf16(kv.z - h2, kv.w - h3));
            uint4 vh, vl;
            vh.x = f2tf32(vv.x); vl.x = f2tf32(vv.x - __uint_as_float(vh.x));
            vh.y = f2tf32(vv.y); vl.y = f2tf32(vv.y - __uint_as_float(vh.y));
            vh.z = f2tf32(vv.z); vl.z = f2tf32(vv.z - __uint_as_float(vh.z));
            vh.w = f2tf32(vv.w); vl.w = f2tf32(vv.w - __uint_as_float(vh.w));
            *(uint4*)&VsH[r * FP + c] = vh;
            *(uint4*)&VsL[r * FP + c] = vl;
        }
        __syncthreads();

        // S = (Q * scale) K^T  -- 3x bf16 (k16)
        float s[8][4];
#pragma unroll
        for (int nt = 0; nt < 8; ++nt)
#pragma unroll
            for (int i = 0; i < 4; ++i) s[nt][i] = 0.f;

#pragma unroll
        for (int ks = 0; ks < 4; ++ks) {
            const int kc = ks * 8;
#pragma unroll
            for (int nt = 0; nt < 8; ++nt) {
                const int br = (nt * 8 + g) * PKW + kc;
                uint32_t bh0 = KsHb[br + tg], bh1 = KsHb[br + tg + 4];
                uint32_t bl0 = KsLb[br + tg], bl1 = KsLb[br + tg + 4];
                mma_bf16(s[nt][0], s[nt][1], s[nt][2], s[nt][3],
                         qh[ks][0], qh[ks][1], qh[ks][2], qh[ks][3], bh0, bh1);
                mma_bf16(s[nt][0], s[nt][1], s[nt][2], s[nt][3],
                         ql[ks][0], ql[ks][1], ql[ks][2], ql[ks][3], bh0, bh1);
                mma_bf16(s[nt][0], s[nt][1], s[nt][2], s[nt][3],
                         qh[ks][0], qh[ks][1], qh[ks][2], qh[ks][3], bl0, bl1);
            }
        }

        // Causal mask (diagonal tile only)
        if (kt == (int)blockIdx.x) {
            const int row0 = qbase + wid * 16 + g;
#pragma unroll
            for (int nt = 0; nt < 8; ++nt) {
                const int c0 = kb + nt * 8 + 2 * tg;
                if (c0     > row0)     s[nt][0] = -CUDART_INF_F;
                if (c0 + 1 > row0)     s[nt][1] = -CUDART_INF_F;
                if (c0     > row0 + 8) s[nt][2] = -CUDART_INF_F;
                if (c0 + 1 > row0 + 8) s[nt][3] = -CUDART_INF_F;
            }
        }

        // Online softmax (exp2 domain)
        float mx0 = -CUDART_INF_F, mx1 = -CUDART_INF_F;
#pragma unroll
        for (int nt = 0; nt < 8; ++nt) {
            mx0 = fmaxf(mx0, fmaxf(s[nt][0], s[nt][1]));
            mx1 = fmaxf(mx1, fmaxf(s[nt][2], s[nt][3]));
        }
        mx0 = fmaxf(mx0, __shfl_xor_sync(0xffffffffu, mx0, 1));
        mx0 = fmaxf(mx0, __shfl_xor_sync(0xffffffffu, mx0, 2));
        mx1 = fmaxf(mx1, __shfl_xor_sync(0xffffffffu, mx1, 1));
        mx1 = fmaxf(mx1, __shfl_xor_sync(0xffffffffu, mx1, 2));

        float mn0 = fmaxf(m0, mx0), mn1 = fmaxf(m1, mx1);
        float cr0 = ex2f(m0 - mn0), cr1 = ex2f(m1 - mn1);
        float sum0 = 0.f, sum1 = 0.f;
        const int prow = (wid * 16 + g) * FP;
#pragma unroll
        for (int nt = 0; nt < 8; ++nt) {
            float p0 = ex2f(s[nt][0] - mn0), p1 = ex2f(s[nt][1] - mn0);
            float p2 = ex2f(s[nt][2] - mn1), p3 = ex2f(s[nt][3] - mn1);
            sum0 += p0 + p1;
            sum1 += p2 + p3;
            uint32_t h0 = f2tf32(p0), h1 = f2tf32(p1);
            uint32_t h2 = f2tf32(p2), h3 = f2tf32(p3);
            const int pc = nt * 8 + 2 * tg;
            *(uint2*)&PsH[prow + pc]          = make_uint2(h0, h1);
            *(uint2*)&PsH[prow + 8 * FP + pc] = make_uint2(h2, h3);
            *(uint2*)&PsL[prow + pc]          = make_uint2(
                f2tf32(p0 - __uint_as_float(h0)), f2tf32(p1 - __uint_as_float(h1)));
            *(uint2*)&PsL[prow + 8 * FP + pc] = make_uint2(
                f2tf32(p2 - __uint_as_float(h2)), f2tf32(p3 - __uint_as_float(h3)));
        }
        sum0 += __shfl_xor_sync(0xffffffffu, sum0, 1);
        sum0 += __shfl_xor_sync(0xffffffffu, sum0, 2);
        sum1 += __shfl_xor_sync(0xffffffffu, sum1, 1);
        sum1 += __shfl_xor_sync(0xffffffffu, sum1, 2);
        l0 = l0 * cr0 + sum0;
        l1 = l1 * cr1 + sum1;
        m0 = mn0; m1 = mn1;
#pragma unroll
        for (int nt = 0; nt < 8; ++nt) {
            o[nt][0] *= cr0; o[nt][1] *= cr0;
            o[nt][2] *= cr1; o[nt][3] *= cr1;
        }
        __syncwarp();

        // O += P V  -- 3x tf32 (k8)
#pragma unroll
        for (int ks = 0; ks < 8; ++ks) {
            const int kc = ks * 8;
            uint32_t ah0 = PsH[prow + kc + tg];
            uint32_t ah1 = PsH[prow + 8 * FP + kc + tg];
            uint32_t ah2 = PsH[prow + kc + tg + 4];
            uint32_t ah3 = PsH[prow + 8 * FP + kc + tg + 4];
            uint32_t al0 = PsL[prow + kc + tg];
            uint32_t al1 = PsL[prow + 8 * FP + kc + tg];
            uint32_t al2 = PsL[prow + kc + tg + 4];
            uint32_t al3 = PsL[prow + 8 * FP + kc + tg + 4];
#pragma unroll
            for (int nt = 0; nt < 8; ++nt) {
                const int vb = (kc + tg) * FP + nt * 8 + g;
                uint32_t bh0 = VsH[vb], bh1 = VsH[vb + 4 * FP];
                uint32_t bl0 = VsL[vb], bl1 = VsL[vb + 4 * FP];
                mma_tf32(o[nt][0], o[nt][1], o[nt][2], o[nt][3],
                         ah0, ah1, ah2, ah3, bh0, bh1);
                mma_tf32(o[nt][0], o[nt][1], o[nt][2], o[nt][3],
                         al0, al1, al2, al3, bh0, bh1);
                mma_tf32(o[nt][0], o[nt][1], o[nt][2], o[nt][3],
                         ah0, ah1, ah2, ah3, bl0, bl1);
            }
        }
        __syncthreads();
    }

    const float i0 = 1.0f / l0, i1 = 1.0f / l1;
    const int row0 = qbase + wid * 16 + g;
#pragma unroll
    for (int nt = 0; nt < 8; ++nt) {
        const int c = nt * 8 + 2 * tg;
        *(float2*)(Og + (size_t)row0 * DD + c) =
            make_float2(o[nt][0] * i0, o[nt][1] * i0);
        *(float2*)(Og + (size_t)(row0 + 8) * DD + c) =
            make_float2(o[nt][2] * i1, o[nt][3] * i1);
    }
}

// ---------------------------------------------------------------------------
extern "C" void kernel_launch(void* const* d_in, const int* in_sizes, int n_in,
                              void* d_out, int out_size)
{
    const float* x   = (const float*)d_in[0];
    const int*   pos = (const int*)  d_in[1];
    const float* Wq  = (const float*)d_in[2];
    const float* Wk  = (const float*)d_in[3];
    const float* Wv  = (const float*)d_in[4];
    const float* Wo  = (const float*)d_in[5];
    float* out = (float*)d_out;

    float *Q, *K, *V, *Aw;
    cudaGetSymbolAddress((void**)&Q,  g_Q);
    cudaGetSymbolAddress((void**)&K,  g_K);
    cudaGetSymbolAddress((void**)&V,  g_V);
    cudaGetSymbolAddress((void**)&Aw, g_A);

    cudaFuncSetAttribute(gemm_tf32, cudaFuncAttributeMaxDynamicSharedMemorySize,
                         G_SMEM);
    cudaFuncSetAttribute(gemm_qkv, cudaFuncAttributeMaxDynamicSharedMemorySize,
                         G_SMEM);
    cudaFuncSetAttribute(flash_mma, cudaFuncAttributeMaxDynamicSharedMemorySize,
                         F_SMEM);

    gemm_qkv<<<dim3(24, BS_ROWS / 128), 128, G_SMEM>>>(x, Wq, Wk, Wv, pos,
                                                       Q, K, V);

    flash_mma<<<dim3(SS / 64, HH, BB), 128, F_SMEM>>>(Q, K, V, Aw);

    gemm_tf32<<<dim3(DD / 128, BS_ROWS / 128), 128, G_SMEM>>>(Aw, Wo, out);
}